// round 7
// baseline (speedup 1.0000x reference)
#include <cuda_runtime.h>
#include <cuda_bf16.h>

#define BB 8
#define SS 1024
#define HH 8
#define DD 128
#define HD 1024

// ---- bf16 hi/lo scratch planes (static device globals) ----
__device__ __nv_bfloat16 g_Xqh[(size_t)BB*SS*128], g_Xql[(size_t)BB*SS*128];
__device__ __nv_bfloat16 g_Xkh[(size_t)BB*SS*128], g_Xkl[(size_t)BB*SS*128];
__device__ __nv_bfloat16 g_Xvh[(size_t)BB*SS*128], g_Xvl[(size_t)BB*SS*128];
__device__ __nv_bfloat16 g_Wqh[HD*128], g_Wql[HD*128];
__device__ __nv_bfloat16 g_Wkh[HD*128], g_Wkl[HD*128];
__device__ __nv_bfloat16 g_Wvh[HD*128], g_Wvl[HD*128];
__device__ __nv_bfloat16 g_Wch[128*HD], g_Wcl[128*HD];
__device__ __nv_bfloat16 g_Qh[(size_t)BB*HH*SS*DD], g_Ql[(size_t)BB*HH*SS*DD];
__device__ __nv_bfloat16 g_Kh[(size_t)BB*HH*SS*DD], g_Kl[(size_t)BB*HH*SS*DD];
__device__ __nv_bfloat16 g_Vh[(size_t)BB*HH*SS*DD], g_Vl[(size_t)BB*HH*SS*DD];
__device__ __nv_bfloat16 g_Oh[(size_t)BB*SS*HD],   g_Ol[(size_t)BB*SS*HD];

// ---- helpers ----
__device__ __forceinline__ void mma16816(float* c, const unsigned* a, const unsigned* b) {
    asm volatile(
        "mma.sync.aligned.m16n8k16.row.col.f32.bf16.bf16.f32 "
        "{%0,%1,%2,%3}, {%4,%5,%6,%7}, {%8,%9}, {%0,%1,%2,%3};\n"
        : "+f"(c[0]), "+f"(c[1]), "+f"(c[2]), "+f"(c[3])
        : "r"(a[0]), "r"(a[1]), "r"(a[2]), "r"(a[3]), "r"(b[0]), "r"(b[1]));
}
__device__ __forceinline__ void ldsm4(unsigned* r, unsigned addr) {
    asm volatile("ldmatrix.sync.aligned.m8n8.x4.shared.b16 {%0,%1,%2,%3}, [%4];"
        : "=r"(r[0]), "=r"(r[1]), "=r"(r[2]), "=r"(r[3]) : "r"(addr));
}
__device__ __forceinline__ void ldsm4t(unsigned* r, unsigned addr) {
    asm volatile("ldmatrix.sync.aligned.m8n8.x4.trans.shared.b16 {%0,%1,%2,%3}, [%4];"
        : "=r"(r[0]), "=r"(r[1]), "=r"(r[2]), "=r"(r[3]) : "r"(addr));
}
__device__ __forceinline__ unsigned cvt2(float hi, float lo) {
    unsigned r;
    asm("cvt.rn.bf16x2.f32 %0, %1, %2;" : "=r"(r) : "f"(hi), "f"(lo));
    return r;
}
__device__ __forceinline__ void packhl(float x0, float x1, unsigned& hi, unsigned& lo) {
    __nv_bfloat16 h0 = __float2bfloat16(x0), h1 = __float2bfloat16(x1);
    hi = ((unsigned)__bfloat16_as_ushort(h1) << 16) | (unsigned)__bfloat16_as_ushort(h0);
    lo = cvt2(x1 - __bfloat162float(h1), x0 - __bfloat162float(h0));
}
__device__ __forceinline__ void cpa(unsigned dst, const void* src) {
    asm volatile("cp.async.cg.shared.global [%0], [%1], 16;" :: "r"(dst), "l"(src));
}
__device__ __forceinline__ void cpa_commit() { asm volatile("cp.async.commit_group;"); }
template<int N> __device__ __forceinline__ void cpa_wait() {
    asm volatile("cp.async.wait_group %0;" :: "n"(N));
}

// ---------------------------------------------------------------------------
// Convert fp32 operands to bf16 hi/lo planes (one-time, memory-bound).
// ---------------------------------------------------------------------------
__global__ __launch_bounds__(256) void convert_kernel(
    const float* __restrict__ q, const float* __restrict__ k, const float* __restrict__ v,
    const float* __restrict__ Wq, const float* __restrict__ Wk, const float* __restrict__ Wv,
    const float* __restrict__ Wc)
{
    const float* src; __nv_bfloat16 *dh, *dl; int n4;
    switch (blockIdx.y) {
        case 0: src = q;  dh = g_Xqh; dl = g_Xql; n4 = BB*SS*128/4; break;
        case 1: src = k;  dh = g_Xkh; dl = g_Xkl; n4 = BB*SS*128/4; break;
        case 2: src = v;  dh = g_Xvh; dl = g_Xvl; n4 = BB*SS*128/4; break;
        case 3: src = Wq; dh = g_Wqh; dl = g_Wql; n4 = HD*128/4; break;
        case 4: src = Wk; dh = g_Wkh; dl = g_Wkl; n4 = HD*128/4; break;
        case 5: src = Wv; dh = g_Wvh; dl = g_Wvl; n4 = HD*128/4; break;
        default: src = Wc; dh = g_Wch; dl = g_Wcl; n4 = 128*HD/4; break;
    }
    for (int i = blockIdx.x*256 + threadIdx.x; i < n4; i += gridDim.x*256) {
        float4 f = ((const float4*)src)[i];
        unsigned h0,l0,h1,l1;
        packhl(f.x, f.y, h0, l0);
        packhl(f.z, f.w, h1, l1);
        ((uint2*)dh)[i] = make_uint2(h0, h1);
        ((uint2*)dl)[i] = make_uint2(l0, l1);
    }
}

// ---------------------------------------------------------------------------
// Fused QKV projection, bf16 hi/lo mma.sync, all-bf16 loads. (unchanged r6)
// ---------------------------------------------------------------------------
__global__ __launch_bounds__(256) void qkv_proj_kernel()
{
    extern __shared__ char smq[];
    const unsigned su = (unsigned)__cvta_generic_to_shared(smq);

    const uint4 *Xh4, *Xl4, *Wh4, *Wl4;
    __nv_bfloat16 *Oh, *Ol;
    if (blockIdx.z == 0)      { Xh4=(const uint4*)g_Xqh; Xl4=(const uint4*)g_Xql;
                                Wh4=(const uint4*)g_Wqh; Wl4=(const uint4*)g_Wql;
                                Oh=g_Qh; Ol=g_Ql; }
    else if (blockIdx.z == 1) { Xh4=(const uint4*)g_Xkh; Xl4=(const uint4*)g_Xkl;
                                Wh4=(const uint4*)g_Wkh; Wl4=(const uint4*)g_Wkl;
                                Oh=g_Kh; Ol=g_Kl; }
    else                      { Xh4=(const uint4*)g_Xvh; Xl4=(const uint4*)g_Xvl;
                                Wh4=(const uint4*)g_Wvh; Wl4=(const uint4*)g_Wvl;
                                Oh=g_Vh; Ol=g_Vl; }

    const int m0 = blockIdx.y * 64;
    const int h  = blockIdx.x;
    const int tid = threadIdx.x;
    const int lane = tid & 31;
    const int wid  = tid >> 5;
    const int band = wid & 3, side = wid >> 2;
    const int g    = lane >> 2, tig = lane & 3;

    #pragma unroll
    for (int t = 0; t < 8; t++) {
        int idx = tid + 256*t;
        int pl = idx >> 10, i2 = idx & 1023;
        int r = i2 >> 4, c = i2 & 15;
        cpa(su + (unsigned)pl*16384u + (unsigned)(r*16 + (c^(r&7)))*16,
            (pl ? Xl4 : Xh4) + (size_t)(m0+r)*16 + c);
    }
    #pragma unroll
    for (int t = 0; t < 16; t++) {
        int idx = tid + 256*t;
        int pl = idx >> 11, i2 = idx & 2047;
        int r = i2 >> 4, c = i2 & 15;
        cpa(su + 32768u + (unsigned)pl*32768u + (unsigned)(r*16 + (c^(r&7)))*16,
            (pl ? Wl4 : Wh4) + (size_t)(h*128+r)*16 + c);
    }
    cpa_commit();
    cpa_wait<0>();
    __syncthreads();

    float acc[8][4];
    #pragma unroll
    for (int nt = 0; nt < 8; nt++)
        #pragma unroll
        for (int c = 0; c < 4; c++) acc[nt][c] = 0.f;

    const int arow = band*16 + (lane & 7) + ((lane >> 3) & 1)*8;
    const int abit = lane >> 4;
    const int kb   = (lane & 7) + ((lane >> 4) & 1)*8;
    const int kbit = (lane >> 3) & 1;

    #pragma unroll
    for (int ks = 0; ks < 8; ks++) {
        unsigned a_h[4], a_l[4];
        unsigned aaddr = su + (unsigned)(arow*16 + ((2*ks+abit) ^ (arow&7)))*16;
        ldsm4(a_h, aaddr);
        ldsm4(a_l, aaddr + 16384u);
        unsigned bh_[4][4], bl_[4][4];
        #pragma unroll
        for (int np = 0; np < 4; np++) {
            int brow = side*64 + np*16 + kb;
            unsigned baddr = su + 32768u + (unsigned)(brow*16 + ((2*ks+kbit) ^ (brow&7)))*16;
            ldsm4(bh_[np], baddr);
            ldsm4(bl_[np], baddr + 32768u);
        }
        #pragma unroll
        for (int np = 0; np < 4; np++) {
            mma16816(acc[2*np],   a_h, bh_[np]);
            mma16816(acc[2*np+1], a_h, bh_[np]+2);
        }
        #pragma unroll
        for (int np = 0; np < 4; np++) {
            mma16816(acc[2*np],   a_h, bl_[np]);
            mma16816(acc[2*np+1], a_h, bl_[np]+2);
        }
        #pragma unroll
        for (int np = 0; np < 4; np++) {
            mma16816(acc[2*np],   a_l, bh_[np]);
            mma16816(acc[2*np+1], a_l, bh_[np]+2);
        }
    }

    #pragma unroll
    for (int nt = 0; nt < 8; nt++) {
        int col = side*64 + nt*8 + 2*tig;
        int ma = m0 + band*16 + g;
        int mb2 = ma + 8;
        size_t offa = (((size_t)((ma  >> 10)*HH + h))*SS + (ma  & 1023))*DD + col;
        size_t offb = (((size_t)((mb2 >> 10)*HH + h))*SS + (mb2 & 1023))*DD + col;
        unsigned hi, lo;
        packhl(acc[nt][0], acc[nt][1], hi, lo);
        *(unsigned*)(Oh + offa) = hi;
        *(unsigned*)(Ol + offa) = lo;
        packhl(acc[nt][2], acc[nt][3], hi, lo);
        *(unsigned*)(Oh + offb) = hi;
        *(unsigned*)(Ol + offb) = lo;
    }
}

// ---------------------------------------------------------------------------
// Flash attention, 512 threads / 16 warps (4/SMSP).
// Warp = (band = wid&7 -> 16 q-rows, dside = wid>>3 -> 64-col D-half).
// QK + softmax identical to validated r4 (full n=64, P in registers, no
// cross-warp exchange; duplicated across the two dside warps of a band).
// PV computes only the warp's D-half (o = 32 regs -> fits 128-reg cap).
// smem identical to r4: msk 0, Qh 4096, Ql 36864, KV0 69632, KV1 135168.
// ---------------------------------------------------------------------------
__global__ __launch_bounds__(512, 1) void attn_kernel(const float* __restrict__ mask)
{
    extern __shared__ char sm[];
    float* msk_s = (float*)sm;
    const unsigned smem_u = (unsigned)__cvta_generic_to_shared(sm);
    const unsigned offQh = 4096u;

    const int tid  = threadIdx.x;
    const int lane = tid & 31;
    const int wid  = tid >> 5;
    const int band = wid & 7;
    const int dside= wid >> 3;
    const int wq0  = band * 16;
    const int g    = lane >> 2;
    const int tig  = lane & 3;

    const int bh = blockIdx.y;
    const int b_ = bh >> 3, h = bh & 7;
    const int q0 = blockIdx.x * 128;

    const uint4* qh4 = (const uint4*)(g_Qh + ((size_t)bh*SS + q0)*DD);
    const uint4* ql4 = (const uint4*)(g_Ql + ((size_t)bh*SS + q0)*DD);
    const uint4* kh4 = (const uint4*)(g_Kh + (size_t)bh*SS*DD);
    const uint4* kl4 = (const uint4*)(g_Kl + (size_t)bh*SS*DD);
    const uint4* vh4 = (const uint4*)(g_Vh + (size_t)bh*SS*DD);
    const uint4* vl4 = (const uint4*)(g_Vl + (size_t)bh*SS*DD);
    const float* mb = mask + b_*SS;

    // mask (1024 floats) + Q planes
    if (tid < 256) ((float4*)msk_s)[tid] = ((const float4*)mb)[tid];
    #pragma unroll
    for (int t = 0; t < 4; t++) {
        int idx = tid + 512*t;
        int r = idx >> 4, c = idx & 15;
        unsigned phys = (unsigned)(r*16 + (c ^ (r&7)))*16;
        *(uint4*)(sm + 4096 + phys)  = qh4[idx];
        *(uint4*)(sm + 36864 + phys) = ql4[idx];
    }
    // prefetch KV block 0 into buf0
    {
        #pragma unroll
        for (int t = 0; t < 2; t++) {
            int idx = tid + 512*t;
            int r = idx >> 4, c = idx & 15;
            unsigned dst = smem_u + 69632u + (unsigned)(r*16 + (c^(r&7)))*16;
            int gi = r*16 + c;
            cpa(dst,          kh4 + gi);
            cpa(dst + 16384u, kl4 + gi);
            cpa(dst + 32768u, vh4 + gi);
            cpa(dst + 49152u, vl4 + gi);
        }
        cpa_commit();
    }

    float o[8][4];
    #pragma unroll
    for (int nt = 0; nt < 8; nt++)
        #pragma unroll
        for (int c = 0; c < 4; c++) o[nt][c] = 0.f;

    float m0s = -3.0e38f, m1s = -3.0e38f, l0s = 0.f, l1s = 0.f;
    const float scale = 0.08838834764831845f;  // 1/sqrt(128)

    const int arow = wq0 + (lane & 7) + ((lane >> 3) & 1)*8;
    const int abit = lane >> 4;
    const int kb   = (lane & 7) + ((lane >> 4) & 1)*8;
    const int kbit = (lane >> 3) & 1;
    const int vr   = (lane & 7) + ((lane >> 3) & 1)*8;
    const int vbit = (lane >> 4) & 1;

    for (int it = 0; it < 16; it++) {
        const int j0 = it*64;
        const unsigned kvcur = (it & 1) ? 135168u : 69632u;
        if (it < 15) {
            const unsigned kvnxt = (it & 1) ? 69632u : 135168u;
            #pragma unroll
            for (int t = 0; t < 2; t++) {
                int idx = tid + 512*t;
                int r = idx >> 4, c = idx & 15;
                unsigned dst = smem_u + kvnxt + (unsigned)(r*16 + (c^(r&7)))*16;
                int gi = (j0 + 64 + r)*16 + c;
                cpa(dst,          kh4 + gi);
                cpa(dst + 16384u, kl4 + gi);
                cpa(dst + 32768u, vh4 + gi);
                cpa(dst + 49152u, vl4 + gi);
            }
            cpa_commit();
            cpa_wait<1>();
        } else {
            cpa_wait<0>();
        }
        __syncthreads();

        // ---- S = Q K^T (full n=64, duplicated across dside pair) ----
        float sacc[8][4];
        #pragma unroll
        for (int nt = 0; nt < 8; nt++)
            #pragma unroll
            for (int c = 0; c < 4; c++) sacc[nt][c] = 0.f;

        #pragma unroll
        for (int ks = 0; ks < 8; ks++) {
            unsigned a_h[4], a_l[4];
            unsigned aaddr = smem_u + offQh + (unsigned)(arow*16 + ((2*ks+abit) ^ (arow&7)))*16;
            ldsm4(a_h, aaddr);
            ldsm4(a_l, aaddr + 32768u);
            unsigned bh_[4][4], bl_[4][4];
            #pragma unroll
            for (int np = 0; np < 4; np++) {
                int brow = np*16 + kb;
                unsigned baddr = smem_u + kvcur + (unsigned)(brow*16 + ((2*ks+kbit) ^ (brow&7)))*16;
                ldsm4(bh_[np], baddr);
                ldsm4(bl_[np], baddr + 16384u);
            }
            #pragma unroll
            for (int np = 0; np < 4; np++) {
                mma16816(sacc[2*np],   a_h, bh_[np]);
                mma16816(sacc[2*np+1], a_h, bh_[np]+2);
            }
            #pragma unroll
            for (int np = 0; np < 4; np++) {
                mma16816(sacc[2*np],   a_h, bl_[np]);
                mma16816(sacc[2*np+1], a_h, bl_[np]+2);
            }
            #pragma unroll
            for (int np = 0; np < 4; np++) {
                mma16816(sacc[2*np],   a_l, bh_[np]);
                mma16816(sacc[2*np+1], a_l, bh_[np]+2);
            }
        }

        // ---- online softmax (identical to r4) ----
        float mx0 = -3.0e38f, mx1 = -3.0e38f;
        #pragma unroll
        for (int nt = 0; nt < 8; nt++) {
            float2 mk = *(float2*)&msk_s[j0 + nt*8 + 2*tig];
            sacc[nt][0] = sacc[nt][0]*scale + mk.x;
            sacc[nt][1] = sacc[nt][1]*scale + mk.y;
            sacc[nt][2] = sacc[nt][2]*scale + mk.x;
            sacc[nt][3] = sacc[nt][3]*scale + mk.y;
            mx0 = fmaxf(mx0, fmaxf(sacc[nt][0], sacc[nt][1]));
            mx1 = fmaxf(mx1, fmaxf(sacc[nt][2], sacc[nt][3]));
        }
        #pragma unroll
        for (int mskb = 1; mskb <= 2; mskb <<= 1) {
            mx0 = fmaxf(mx0, __shfl_xor_sync(0xffffffffu, mx0, mskb));
            mx1 = fmaxf(mx1, __shfl_xor_sync(0xffffffffu, mx1, mskb));
        }
        float mn0 = fmaxf(m0s, mx0), mn1 = fmaxf(m1s, mx1);
        float al0 = __expf(m0s - mn0), al1 = __expf(m1s - mn1);
        m0s = mn0; m1s = mn1;

        float sum0 = 0.f, sum1 = 0.f;
        #pragma unroll
        for (int nt = 0; nt < 8; nt++) {
            float p0 = __expf(sacc[nt][0] - mn0);
            float p1 = __expf(sacc[nt][1] - mn0);
            float p2 = __expf(sacc[nt][2] - mn1);
            float p3 = __expf(sacc[nt][3] - mn1);
            sacc[nt][0] = p0; sacc[nt][1] = p1; sacc[nt][2] = p2; sacc[nt][3] = p3;
            sum0 += p0 + p1; sum1 += p2 + p3;
        }
        #pragma unroll
        for (int mskb = 1; mskb <= 2; mskb <<= 1) {
            sum0 += __shfl_xor_sync(0xffffffffu, sum0, mskb);
            sum1 += __shfl_xor_sync(0xffffffffu, sum1, mskb);
        }
        l0s = l0s*al0 + sum0;
        l1s = l1s*al1 + sum1;

        #pragma unroll
        for (int nt = 0; nt < 8; nt++) {
            o[nt][0] *= al0; o[nt][1] *= al0;
            o[nt][2] *= al1; o[nt][3] *= al1;
        }

        // ---- O += P V (only this warp's D-half: 4 n-pairs) ----
        #pragma unroll
        for (int kk = 0; kk < 4; kk++) {
            unsigned pah[4], pal[4];
            #pragma unroll
            for (int half = 0; half < 2; half++) {
                int nt = 2*kk + half;
                float p0 = sacc[nt][0], p1 = sacc[nt][1];
                float p2 = sacc[nt][2], p3 = sacc[nt][3];
                float h0 = __bfloat162float(__float2bfloat16(p0));
                float h1 = __bfloat162float(__float2bfloat16(p1));
                float h2 = __bfloat162float(__float2bfloat16(p2));
                float h3 = __bfloat162float(__float2bfloat16(p3));
                pah[2*half]   = cvt2(p1, p0);
                pah[2*half+1] = cvt2(p3, p2);
                pal[2*half]   = cvt2(p1 - h1, p0 - h0);
                pal[2*half+1] = cvt2(p3 - h3, p2 - h2);
            }
            int vrow = kk*16 + vr;
            #pragma unroll
            for (int np = 0; np < 4; np++) {
                int vchk = dside*8 + 2*np + vbit;
                unsigned vaddr = smem_u + kvcur + 32768u
                               + (unsigned)(vrow*16 + (vchk ^ (vrow&7)))*16;
                unsigned vbh[4], vbl[4];
                ldsm4t(vbh, vaddr);
                ldsm4t(vbl, vaddr + 16384u);
                mma16816(o[2*np],   pah, vbh);
                mma16816(o[2*np+1], pah, vbh+2);
                mma16816(o[2*np],   pah, vbl);
                mma16816(o[2*np+1], pah, vbl+2);
                mma16816(o[2*np],   pal, vbh);
                mma16816(o[2*np+1], pal, vbh+2);
            }
        }
        __syncthreads();
    }

    // epilogue: normalize, write hi/lo bf16 planes of O (concat [B,S,H*D])
    float inv0 = 1.f / (l0s + 1e-12f);
    float inv1 = 1.f / (l1s + 1e-12f);
    int r0 = q0 + wq0 + g;
    size_t base0 = ((size_t)(b_*SS + r0))*HD + h*DD;
    size_t base1 = base0 + (size_t)8*HD;
    #pragma unroll
    for (int nt = 0; nt < 8; nt++) {
        int cc = dside*64 + nt*8 + 2*tig;
        unsigned hi, lo;
        packhl(o[nt][0]*inv0, o[nt][1]*inv0, hi, lo);
        *(unsigned*)(g_Oh + base0 + cc) = hi;
        *(unsigned*)(g_Ol + base0 + cc) = lo;
        packhl(o[nt][2]*inv1, o[nt][3]*inv1, hi, lo);
        *(unsigned*)(g_Oh + base1 + cc) = hi;
        *(unsigned*)(g_Ol + base1 + cc) = lo;
    }
}

// ---------------------------------------------------------------------------
// Output projection, bf16 hi/lo mma.sync, 64x64 tiles -> grid 256.
// smem: Ah 0 (16K), Al 16384, Bh 32768 (16K), Bl 49152  (64KB total).
// ---------------------------------------------------------------------------
__global__ __launch_bounds__(256) void out_proj_kernel(
    const float* __restrict__ bc, float* __restrict__ out)
{
    extern __shared__ char smo[];
    const unsigned su = (unsigned)__cvta_generic_to_shared(smo);

    const int m0 = blockIdx.x * 64;
    const int n0 = blockIdx.y * 64;
    const int tid = threadIdx.x;
    const int lane = tid & 31;
    const int wid  = tid >> 5;
    const int mrow0 = (wid & 3)*16;
    const int ncol0 = (wid >> 2)*32;
    const int g = lane >> 2, tig = lane & 3;

    const int arow = mrow0 + (lane & 7) + ((lane >> 3) & 1)*8;
    const int abit = lane >> 4;
    const int kb   = (lane & 7) + ((lane >> 4) & 1)*8;
    const int kbit = (lane >> 3) & 1;

    float acc[4][4];
    #pragma unroll
    for (int nt = 0; nt < 4; nt++)
        #pragma unroll
        for (int c = 0; c < 4; c++) acc[nt][c] = 0.f;

    const uint4* Ah4 = (const uint4*)g_Oh;
    const uint4* Al4 = (const uint4*)g_Ol;
    const uint4* Bh4 = (const uint4*)g_Wch;
    const uint4* Bl4 = (const uint4*)g_Wcl;

    for (int kc = 0; kc < HD; kc += 128) {
        __syncthreads();
        #pragma unroll
        for (int t = 0; t < 8; t++) {
            int idx = tid + 256*t;
            int pl = idx >> 10, i2 = idx & 1023;
            int r = i2 >> 4, c = i2 & 15;
            cpa(su + (unsigned)pl*16384u + (unsigned)(r*16 + (c^(r&7)))*16,
                (pl ? Al4 : Ah4) + (size_t)(m0+r)*(HD/8) + kc/8 + c);
        }
        #pragma unroll
        for (int t = 0; t < 8; t++) {
            int idx = tid + 256*t;
            int pl = idx >> 10, i2 = idx & 1023;
            int r = i2 >> 4, c = i2 & 15;
            cpa(su + 32768u + (unsigned)pl*16384u + (unsigned)(r*16 + (c^(r&7)))*16,
                (pl ? Bl4 : Bh4) + (size_t)(n0+r)*(HD/8) + kc/8 + c);
        }
        cpa_commit();
        cpa_wait<0>();
        __syncthreads();

        #pragma unroll
        for (int ks = 0; ks < 8; ks++) {
            unsigned a_h[4], a_l[4];
            unsigned aaddr = su + (unsigned)(arow*16 + ((2*ks+abit) ^ (arow&7)))*16;
            ldsm4(a_h, aaddr);
            ldsm4(a_l, aaddr + 16384u);
            unsigned bh_[2][4], bl_[2][4];
            #pragma unroll
            for (int np = 0; np < 2; np++) {
                int brow = ncol0 + np*16 + kb;
                unsigned baddr = su + 32768u + (unsigned)(brow*16 + ((2*ks+kbit) ^ (brow&7)))*16;
                ldsm4(bh_[np], baddr);
                ldsm4(bl_[np], baddr + 16384u);
            }
            #pragma unroll
            for (int np = 0; np < 2; np++) {
                mma16816(acc[2*np],   a_h, bh_[np]);
                mma16816(acc[2*np+1], a_h, bh_[np]+2);
            }
            #pragma unroll
            for (int np = 0; np < 2; np++) {
                mma16816(acc[2*np],   a_h, bl_[np]);
                mma16816(acc[2*np+1], a_h, bl_[np]+2);
            }
            #pragma unroll
            for (int np = 0; np < 2; np++) {
                mma16816(acc[2*np],   a_l, bh_[np]);
                mma16816(acc[2*np+1], a_l, bh_[np]+2);
            }
        }
    }

    #pragma unroll
    for (int nt = 0; nt < 4; nt++) {
        int n = n0 + ncol0 + nt*8 + 2*tig;
        float2 bb = *(const float2*)(bc + n);
        int ma = m0 + mrow0 + g;
        *(float2*)(out + (size_t)ma*128 + n) =
            make_float2(acc[nt][0] + bb.x, acc[nt][1] + bb.y);
        *(float2*)(out + (size_t)(ma+8)*128 + n) =
            make_float2(acc[nt][2] + bb.x, acc[nt][3] + bb.y);
    }
}

// ---------------------------------------------------------------------------
extern "C" void kernel_launch(void* const* d_in, const int* in_sizes, int n_in,
                              void* d_out, int out_size)
{
    const float* q    = (const float*)d_in[0];
    const float* k    = (const float*)d_in[1];
    const float* v    = (const float*)d_in[2];
    const float* mask = (const float*)d_in[3];
    const float* Wq   = (const float*)d_in[4];
    const float* Wk   = (const float*)d_in[5];
    const float* Wv   = (const float*)d_in[6];
    const float* Wc   = (const float*)d_in[7];
    const float* bc   = (const float*)d_in[8];
    float* out = (float*)d_out;

    const int qkv_smem  = 98304;
    const int attn_smem = 200704;
    const int outp_smem = 65536;

    cudaFuncSetAttribute(qkv_proj_kernel, cudaFuncAttributeMaxDynamicSharedMemorySize, qkv_smem);
    cudaFuncSetAttribute(attn_kernel, cudaFuncAttributeMaxDynamicSharedMemorySize, attn_smem);
    cudaFuncSetAttribute(out_proj_kernel, cudaFuncAttributeMaxDynamicSharedMemorySize, outp_smem);

    convert_kernel<<<dim3(96, 7), 256>>>(q, k, v, Wq, Wk, Wv, Wc);
    qkv_proj_kernel<<<dim3(8, 128, 3), 256, qkv_smem>>>();
    attn_kernel<<<dim3(8, 64), 512, attn_smem>>>(mask);
    out_proj_kernel<<<dim3(128, 2), 256, outp_smem>>>(bc, out);
}

// round 9
// speedup vs baseline: 1.8694x; 1.8694x over previous
#include <cuda_runtime.h>
#include <cuda_bf16.h>
#include <cuda_fp16.h>

#define BB 8
#define SS 1024
#define HH 8
#define DD 128
#define HD 1024

// ---- scratch planes (static device globals; 16-bit payload, type-punned) ----
__device__ __nv_bfloat16 g_Xqh[(size_t)BB*SS*128], g_Xql[(size_t)BB*SS*128];
__device__ __nv_bfloat16 g_Xkh[(size_t)BB*SS*128], g_Xkl[(size_t)BB*SS*128];
__device__ __nv_bfloat16 g_Xvh[(size_t)BB*SS*128], g_Xvl[(size_t)BB*SS*128];
__device__ __nv_bfloat16 g_Wqh[HD*128], g_Wql[HD*128];
__device__ __nv_bfloat16 g_Wkh[HD*128], g_Wkl[HD*128];
__device__ __nv_bfloat16 g_Wvh[HD*128], g_Wvl[HD*128];
__device__ __nv_bfloat16 g_Wch[128*HD], g_Wcl[128*HD];
__device__ __nv_bfloat16 g_Qh[(size_t)BB*HH*SS*DD], g_Ql[(size_t)BB*HH*SS*DD];
__device__ __nv_bfloat16 g_Kh[(size_t)BB*HH*SS*DD], g_Kl[(size_t)BB*HH*SS*DD];
__device__ __nv_bfloat16 g_Vh[(size_t)BB*HH*SS*DD], g_Vl[(size_t)BB*HH*SS*DD]; // fp16 payload
__device__ __nv_bfloat16 g_Oh[(size_t)BB*SS*HD],   g_Ol[(size_t)BB*SS*HD];

// ---- helpers ----
__device__ __forceinline__ void mma16816(float* c, const unsigned* a, const unsigned* b) {
    asm volatile(
        "mma.sync.aligned.m16n8k16.row.col.f32.bf16.bf16.f32 "
        "{%0,%1,%2,%3}, {%4,%5,%6,%7}, {%8,%9}, {%0,%1,%2,%3};\n"
        : "+f"(c[0]), "+f"(c[1]), "+f"(c[2]), "+f"(c[3])
        : "r"(a[0]), "r"(a[1]), "r"(a[2]), "r"(a[3]), "r"(b[0]), "r"(b[1]));
}
__device__ __forceinline__ void mma16816h(float* c, const unsigned* a, const unsigned* b) {
    asm volatile(
        "mma.sync.aligned.m16n8k16.row.col.f32.f16.f16.f32 "
        "{%0,%1,%2,%3}, {%4,%5,%6,%7}, {%8,%9}, {%0,%1,%2,%3};\n"
        : "+f"(c[0]), "+f"(c[1]), "+f"(c[2]), "+f"(c[3])
        : "r"(a[0]), "r"(a[1]), "r"(a[2]), "r"(a[3]), "r"(b[0]), "r"(b[1]));
}
__device__ __forceinline__ void ldsm4(unsigned* r, unsigned addr) {
    asm volatile("ldmatrix.sync.aligned.m8n8.x4.shared.b16 {%0,%1,%2,%3}, [%4];"
        : "=r"(r[0]), "=r"(r[1]), "=r"(r[2]), "=r"(r[3]) : "r"(addr));
}
__device__ __forceinline__ void ldsm4t(unsigned* r, unsigned addr) {
    asm volatile("ldmatrix.sync.aligned.m8n8.x4.trans.shared.b16 {%0,%1,%2,%3}, [%4];"
        : "=r"(r[0]), "=r"(r[1]), "=r"(r[2]), "=r"(r[3]) : "r"(addr));
}
__device__ __forceinline__ unsigned cvt2(float hi, float lo) {
    unsigned r;
    asm("cvt.rn.bf16x2.f32 %0, %1, %2;" : "=r"(r) : "f"(hi), "f"(lo));
    return r;
}
__device__ __forceinline__ unsigned cvth2(float hi, float lo) {
    unsigned r;
    asm("cvt.rn.f16x2.f32 %0, %1, %2;" : "=r"(r) : "f"(hi), "f"(lo));
    return r;
}
__device__ __forceinline__ void packhl(float x0, float x1, unsigned& hi, unsigned& lo) {
    __nv_bfloat16 h0 = __float2bfloat16(x0), h1 = __float2bfloat16(x1);
    hi = ((unsigned)__bfloat16_as_ushort(h1) << 16) | (unsigned)__bfloat16_as_ushort(h0);
    lo = cvt2(x1 - __bfloat162float(h1), x0 - __bfloat162float(h0));
}
__device__ __forceinline__ void packhl_h(float x0, float x1, unsigned& hi, unsigned& lo) {
    __half h0 = __float2half_rn(x0), h1 = __float2half_rn(x1);
    hi = ((unsigned)__half_as_ushort(h1) << 16) | (unsigned)__half_as_ushort(h0);
    lo = cvth2(x1 - __half2float(h1), x0 - __half2float(h0));
}
__device__ __forceinline__ void cpa(unsigned dst, const void* src) {
    asm volatile("cp.async.cg.shared.global [%0], [%1], 16;" :: "r"(dst), "l"(src));
}
__device__ __forceinline__ void cpa_commit() { asm volatile("cp.async.commit_group;"); }
template<int N> __device__ __forceinline__ void cpa_wait() {
    asm volatile("cp.async.wait_group %0;" :: "n"(N));
}

// ---------------------------------------------------------------------------
// Convert fp32 operands to bf16 hi/lo planes (one-time, memory-bound).
// ---------------------------------------------------------------------------
__global__ __launch_bounds__(256) void convert_kernel(
    const float* __restrict__ q, const float* __restrict__ k, const float* __restrict__ v,
    const float* __restrict__ Wq, const float* __restrict__ Wk, const float* __restrict__ Wv,
    const float* __restrict__ Wc)
{
    const float* src; __nv_bfloat16 *dh, *dl; int n4;
    switch (blockIdx.y) {
        case 0: src = q;  dh = g_Xqh; dl = g_Xql; n4 = BB*SS*128/4; break;
        case 1: src = k;  dh = g_Xkh; dl = g_Xkl; n4 = BB*SS*128/4; break;
        case 2: src = v;  dh = g_Xvh; dl = g_Xvl; n4 = BB*SS*128/4; break;
        case 3: src = Wq; dh = g_Wqh; dl = g_Wql; n4 = HD*128/4; break;
        case 4: src = Wk; dh = g_Wkh; dl = g_Wkl; n4 = HD*128/4; break;
        case 5: src = Wv; dh = g_Wvh; dl = g_Wvl; n4 = HD*128/4; break;
        default: src = Wc; dh = g_Wch; dl = g_Wcl; n4 = 128*HD/4; break;
    }
    for (int i = blockIdx.x*256 + threadIdx.x; i < n4; i += gridDim.x*256) {
        float4 f = ((const float4*)src)[i];
        unsigned h0,l0,h1,l1;
        packhl(f.x, f.y, h0, l0);
        packhl(f.z, f.w, h1, l1);
        ((uint2*)dh)[i] = make_uint2(h0, h1);
        ((uint2*)dl)[i] = make_uint2(l0, l1);
    }
}

// ---------------------------------------------------------------------------
// Fused QKV projection (validated r6). Only delta: V output packs fp16 planes.
// ---------------------------------------------------------------------------
__global__ __launch_bounds__(256) void qkv_proj_kernel()
{
    extern __shared__ char smq[];
    const unsigned su = (unsigned)__cvta_generic_to_shared(smq);

    const uint4 *Xh4, *Xl4, *Wh4, *Wl4;
    __nv_bfloat16 *Oh, *Ol;
    if (blockIdx.z == 0)      { Xh4=(const uint4*)g_Xqh; Xl4=(const uint4*)g_Xql;
                                Wh4=(const uint4*)g_Wqh; Wl4=(const uint4*)g_Wql;
                                Oh=g_Qh; Ol=g_Ql; }
    else if (blockIdx.z == 1) { Xh4=(const uint4*)g_Xkh; Xl4=(const uint4*)g_Xkl;
                                Wh4=(const uint4*)g_Wkh; Wl4=(const uint4*)g_Wkl;
                                Oh=g_Kh; Ol=g_Kl; }
    else                      { Xh4=(const uint4*)g_Xvh; Xl4=(const uint4*)g_Xvl;
                                Wh4=(const uint4*)g_Wvh; Wl4=(const uint4*)g_Wvl;
                                Oh=g_Vh; Ol=g_Vl; }
    const bool vmode = (blockIdx.z == 2);

    const int m0 = blockIdx.y * 64;
    const int h  = blockIdx.x;
    const int tid = threadIdx.x;
    const int lane = tid & 31;
    const int wid  = tid >> 5;
    const int band = wid & 3, side = wid >> 2;
    const int g    = lane >> 2, tig = lane & 3;

    #pragma unroll
    for (int t = 0; t < 8; t++) {
        int idx = tid + 256*t;
        int pl = idx >> 10, i2 = idx & 1023;
        int r = i2 >> 4, c = i2 & 15;
        cpa(su + (unsigned)pl*16384u + (unsigned)(r*16 + (c^(r&7)))*16,
            (pl ? Xl4 : Xh4) + (size_t)(m0+r)*16 + c);
    }
    #pragma unroll
    for (int t = 0; t < 16; t++) {
        int idx = tid + 256*t;
        int pl = idx >> 11, i2 = idx & 2047;
        int r = i2 >> 4, c = i2 & 15;
        cpa(su + 32768u + (unsigned)pl*32768u + (unsigned)(r*16 + (c^(r&7)))*16,
            (pl ? Wl4 : Wh4) + (size_t)(h*128+r)*16 + c);
    }
    cpa_commit();
    cpa_wait<0>();
    __syncthreads();

    float acc[8][4];
    #pragma unroll
    for (int nt = 0; nt < 8; nt++)
        #pragma unroll
        for (int c = 0; c < 4; c++) acc[nt][c] = 0.f;

    const int arow = band*16 + (lane & 7) + ((lane >> 3) & 1)*8;
    const int abit = lane >> 4;
    const int kb   = (lane & 7) + ((lane >> 4) & 1)*8;
    const int kbit = (lane >> 3) & 1;

    #pragma unroll
    for (int ks = 0; ks < 8; ks++) {
        unsigned a_h[4], a_l[4];
        unsigned aaddr = su + (unsigned)(arow*16 + ((2*ks+abit) ^ (arow&7)))*16;
        ldsm4(a_h, aaddr);
        ldsm4(a_l, aaddr + 16384u);
        unsigned bh_[4][4], bl_[4][4];
        #pragma unroll
        for (int np = 0; np < 4; np++) {
            int brow = side*64 + np*16 + kb;
            unsigned baddr = su + 32768u + (unsigned)(brow*16 + ((2*ks+kbit) ^ (brow&7)))*16;
            ldsm4(bh_[np], baddr);
            ldsm4(bl_[np], baddr + 32768u);
        }
        #pragma unroll
        for (int np = 0; np < 4; np++) {
            mma16816(acc[2*np],   a_h, bh_[np]);
            mma16816(acc[2*np+1], a_h, bh_[np]+2);
        }
        #pragma unroll
        for (int np = 0; np < 4; np++) {
            mma16816(acc[2*np],   a_h, bl_[np]);
            mma16816(acc[2*np+1], a_h, bl_[np]+2);
        }
        #pragma unroll
        for (int np = 0; np < 4; np++) {
            mma16816(acc[2*np],   a_l, bh_[np]);
            mma16816(acc[2*np+1], a_l, bh_[np]+2);
        }
    }

    #pragma unroll
    for (int nt = 0; nt < 8; nt++) {
        int col = side*64 + nt*8 + 2*tig;
        int ma = m0 + band*16 + g;
        int mb2 = ma + 8;
        size_t offa = (((size_t)((ma  >> 10)*HH + h))*SS + (ma  & 1023))*DD + col;
        size_t offb = (((size_t)((mb2 >> 10)*HH + h))*SS + (mb2 & 1023))*DD + col;
        unsigned hi, lo;
        if (vmode) packhl_h(acc[nt][0], acc[nt][1], hi, lo);
        else       packhl  (acc[nt][0], acc[nt][1], hi, lo);
        *(unsigned*)(Oh + offa) = hi;
        *(unsigned*)(Ol + offa) = lo;
        if (vmode) packhl_h(acc[nt][2], acc[nt][3], hi, lo);
        else       packhl  (acc[nt][2], acc[nt][3], hi, lo);
        *(unsigned*)(Oh + offb) = hi;
        *(unsigned*)(Ol + offb) = lo;
    }
}

// ---------------------------------------------------------------------------
// Flash attention (r6 structure): QK single-term bf16, PV fp16 2-term.
// 256 thr / 8 warps, cp.async double-buffered K/V.
// smem: msk 0 (4KB), Qh 4096 (32KB), KV0 36864, KV1 86016.
// KV buf: Kh+0 (16KB), Vh+16384 (16KB), Vl+32768 (16KB) = 48KB.
// ---------------------------------------------------------------------------
__global__ __launch_bounds__(256, 1) void attn_kernel(const float* __restrict__ mask)
{
    extern __shared__ char sm[];
    float* msk_s = (float*)sm;
    const unsigned smem_u = (unsigned)__cvta_generic_to_shared(sm);
    const unsigned offQh = 4096u, KV0 = 36864u, KV1 = 86016u;

    const int tid  = threadIdx.x;
    const int lane = tid & 31;
    const int wid  = tid >> 5;
    const int wq0  = wid * 16;
    const int g    = lane >> 2;
    const int tig  = lane & 3;

    const int bh = blockIdx.y;
    const int b_ = bh >> 3, h = bh & 7;
    const int q0 = blockIdx.x * 128;

    const uint4* qh4 = (const uint4*)(g_Qh + ((size_t)bh*SS + q0)*DD);
    const uint4* kh4 = (const uint4*)(g_Kh + (size_t)bh*SS*DD);
    const uint4* vh4 = (const uint4*)(g_Vh + (size_t)bh*SS*DD);
    const uint4* vl4 = (const uint4*)(g_Vl + (size_t)bh*SS*DD);
    const float* mb = mask + b_*SS;

    // mask (1024 floats) + Qh plane
    *(float4*)&msk_s[tid*4] = ((const float4*)mb)[tid];
    #pragma unroll
    for (int t = 0; t < 8; t++) {
        int idx = tid + 256*t;
        int r = idx >> 4, c = idx & 15;
        unsigned phys = (unsigned)(r*16 + (c ^ (r&7)))*16;
        *(uint4*)(sm + 4096 + phys) = qh4[idx];
    }
    // prefetch KV block 0 into buf0
    {
        #pragma unroll
        for (int t = 0; t < 4; t++) {
            int idx = tid + 256*t;
            int r = idx >> 4, c = idx & 15;
            unsigned dst = smem_u + KV0 + (unsigned)(r*16 + (c^(r&7)))*16;
            cpa(dst,          kh4 + idx);
            cpa(dst + 16384u, vh4 + idx);
            cpa(dst + 32768u, vl4 + idx);
        }
        cpa_commit();
    }

    float o[16][4];
    #pragma unroll
    for (int nt = 0; nt < 16; nt++)
        #pragma unroll
        for (int c = 0; c < 4; c++) o[nt][c] = 0.f;

    float m0s = -3.0e38f, m1s = -3.0e38f, l0s = 0.f, l1s = 0.f;
    const float scale = 0.08838834764831845f;  // 1/sqrt(128)

    const int arow = wq0 + (lane & 7) + ((lane >> 3) & 1)*8;
    const int abit = lane >> 4;
    const int kbr  = (lane & 7) + ((lane >> 4) & 1)*8;
    const int kbit = (lane >> 3) & 1;
    const int vr   = (lane & 7) + ((lane >> 3) & 1)*8;
    const int vbit = (lane >> 4) & 1;

    for (int it = 0; it < 16; it++) {
        const int j0 = it*64;
        const unsigned kvcur = (it & 1) ? KV1 : KV0;
        if (it < 15) {
            const unsigned kvnxt = (it & 1) ? KV0 : KV1;
            #pragma unroll
            for (int t = 0; t < 4; t++) {
                int idx = tid + 256*t;
                int r = idx >> 4, c = idx & 15;
                unsigned dst = smem_u + kvnxt + (unsigned)(r*16 + (c^(r&7)))*16;
                int gi = (j0 + 64 + r)*16 + c;
                cpa(dst,          kh4 + gi);
                cpa(dst + 16384u, vh4 + gi);
                cpa(dst + 32768u, vl4 + gi);
            }
            cpa_commit();
            cpa_wait<1>();
        } else {
            cpa_wait<0>();
        }
        __syncthreads();

        // ---- S = Q K^T (single-term bf16) ----
        float sacc[8][4];
        #pragma unroll
        for (int nt = 0; nt < 8; nt++)
            #pragma unroll
            for (int c = 0; c < 4; c++) sacc[nt][c] = 0.f;

        #pragma unroll
        for (int ks = 0; ks < 8; ks++) {
            unsigned a_h[4];
            unsigned aaddr = smem_u + offQh + (unsigned)(arow*16 + ((2*ks+abit) ^ (arow&7)))*16;
            ldsm4(a_h, aaddr);
            unsigned bh_[4][4];
            #pragma unroll
            for (int np = 0; np < 4; np++) {
                int brow = np*16 + kbr;
                unsigned baddr = smem_u + kvcur + (unsigned)(brow*16 + ((2*ks+kbit) ^ (brow&7)))*16;
                ldsm4(bh_[np], baddr);
            }
            #pragma unroll
            for (int np = 0; np < 4; np++) {
                mma16816(sacc[2*np],   a_h, bh_[np]);
                mma16816(sacc[2*np+1], a_h, bh_[np]+2);
            }
        }

        // ---- online softmax (identical r4/r6) ----
        float mx0 = -3.0e38f, mx1 = -3.0e38f;
        #pragma unroll
        for (int nt = 0; nt < 8; nt++) {
            float2 mk = *(float2*)&msk_s[j0 + nt*8 + 2*tig];
            sacc[nt][0] = sacc[nt][0]*scale + mk.x;
            sacc[nt][1] = sacc[nt][1]*scale + mk.y;
            sacc[nt][2] = sacc[nt][2]*scale + mk.x;
            sacc[nt][3] = sacc[nt][3]*scale + mk.y;
            mx0 = fmaxf(mx0, fmaxf(sacc[nt][0], sacc[nt][1]));
            mx1 = fmaxf(mx1, fmaxf(sacc[nt][2], sacc[nt][3]));
        }
        #pragma unroll
        for (int mskb = 1; mskb <= 2; mskb <<= 1) {
            mx0 = fmaxf(mx0, __shfl_xor_sync(0xffffffffu, mx0, mskb));
            mx1 = fmaxf(mx1, __shfl_xor_sync(0xffffffffu, mx1, mskb));
        }
        float mn0 = fmaxf(m0s, mx0), mn1 = fmaxf(m1s, mx1);
        float al0 = __expf(m0s - mn0), al1 = __expf(m1s - mn1);
        m0s = mn0; m1s = mn1;

        float sum0 = 0.f, sum1 = 0.f;
        #pragma unroll
        for (int nt = 0; nt < 8; nt++) {
            float p0 = __expf(sacc[nt][0] - mn0);
            float p1 = __expf(sacc[nt][1] - mn0);
            float p2 = __expf(sacc[nt][2] - mn1);
            float p3 = __expf(sacc[nt][3] - mn1);
            sacc[nt][0] = p0; sacc[nt][1] = p1; sacc[nt][2] = p2; sacc[nt][3] = p3;
            sum0 += p0 + p1; sum1 += p2 + p3;
        }
        #pragma unroll
        for (int mskb = 1; mskb <= 2; mskb <<= 1) {
            sum0 += __shfl_xor_sync(0xffffffffu, sum0, mskb);
            sum1 += __shfl_xor_sync(0xffffffffu, sum1, mskb);
        }
        l0s = l0s*al0 + sum0;
        l1s = l1s*al1 + sum1;

        #pragma unroll
        for (int nt = 0; nt < 16; nt++) {
            o[nt][0] *= al0; o[nt][1] *= al0;
            o[nt][2] *= al1; o[nt][3] *= al1;
        }

        // ---- O += P V (fp16: P single, V hi+lo) ----
        #pragma unroll
        for (int kk = 0; kk < 4; kk++) {
            unsigned pah[4];
            #pragma unroll
            for (int half = 0; half < 2; half++) {
                int nt = 2*kk + half;
                pah[2*half]   = cvth2(sacc[nt][1], sacc[nt][0]);
                pah[2*half+1] = cvth2(sacc[nt][3], sacc[nt][2]);
            }
            int vrow = kk*16 + vr;
            #pragma unroll
            for (int np = 0; np < 8; np++) {
                int vchk = 2*np + vbit;
                unsigned vaddr = smem_u + kvcur + 16384u
                               + (unsigned)(vrow*16 + (vchk ^ (vrow&7)))*16;
                unsigned vbh[4], vbl[4];
                ldsm4t(vbh, vaddr);
                ldsm4t(vbl, vaddr + 16384u);
                mma16816h(o[2*np],   pah, vbh);
                mma16816h(o[2*np+1], pah, vbh+2);
                mma16816h(o[2*np],   pah, vbl);
                mma16816h(o[2*np+1], pah, vbl+2);
            }
        }
        __syncthreads();
    }

    // epilogue: normalize, write hi/lo bf16 planes of O (concat [B,S,H*D])
    float inv0 = 1.f / (l0s + 1e-12f);
    float inv1 = 1.f / (l1s + 1e-12f);
    int r0 = q0 + wq0 + g;
    size_t base0 = ((size_t)(b_*SS + r0))*HD + h*DD;
    size_t base1 = base0 + (size_t)8*HD;
    #pragma unroll
    for (int nt = 0; nt < 16; nt++) {
        int cc = nt*8 + 2*tig;
        unsigned hi, lo;
        packhl(o[nt][0]*inv0, o[nt][1]*inv0, hi, lo);
        *(unsigned*)(g_Oh + base0 + cc) = hi;
        *(unsigned*)(g_Ol + base0 + cc) = lo;
        packhl(o[nt][2]*inv1, o[nt][3]*inv1, hi, lo);
        *(unsigned*)(g_Oh + base1 + cc) = hi;
        *(unsigned*)(g_Ol + base1 + cc) = lo;
    }
}

// ---------------------------------------------------------------------------
// Output projection (validated r7): bf16 hi/lo mma.sync, 64x64 tiles, grid 256.
// ---------------------------------------------------------------------------
__global__ __launch_bounds__(256) void out_proj_kernel(
    const float* __restrict__ bc, float* __restrict__ out)
{
    extern __shared__ char smo[];
    const unsigned su = (unsigned)__cvta_generic_to_shared(smo);

    const int m0 = blockIdx.x * 64;
    const int n0 = blockIdx.y * 64;
    const int tid = threadIdx.x;
    const int lane = tid & 31;
    const int wid  = tid >> 5;
    const int mrow0 = (wid & 3)*16;
    const int ncol0 = (wid >> 2)*32;
    const int g = lane >> 2, tig = lane & 3;

    const int arow = mrow0 + (lane & 7) + ((lane >> 3) & 1)*8;
    const int abit = lane >> 4;
    const int kb   = (lane & 7) + ((lane >> 4) & 1)*8;
    const int kbit = (lane >> 3) & 1;

    float acc[4][4];
    #pragma unroll
    for (int nt = 0; nt < 4; nt++)
        #pragma unroll
        for (int c = 0; c < 4; c++) acc[nt][c] = 0.f;

    const uint4* Ah4 = (const uint4*)g_Oh;
    const uint4* Al4 = (const uint4*)g_Ol;
    const uint4* Bh4 = (const uint4*)g_Wch;
    const uint4* Bl4 = (const uint4*)g_Wcl;

    for (int kc = 0; kc < HD; kc += 128) {
        __syncthreads();
        #pragma unroll
        for (int t = 0; t < 8; t++) {
            int idx = tid + 256*t;
            int pl = idx >> 10, i2 = idx & 1023;
            int r = i2 >> 4, c = i2 & 15;
            cpa(su + (unsigned)pl*16384u + (unsigned)(r*16 + (c^(r&7)))*16,
                (pl ? Al4 : Ah4) + (size_t)(m0+r)*(HD/8) + kc/8 + c);
        }
        #pragma unroll
        for (int t = 0; t < 8; t++) {
            int idx = tid + 256*t;
            int pl = idx >> 10, i2 = idx & 1023;
            int r = i2 >> 4, c = i2 & 15;
            cpa(su + 32768u + (unsigned)pl*16384u + (unsigned)(r*16 + (c^(r&7)))*16,
                (pl ? Bl4 : Bh4) + (size_t)(n0+r)*(HD/8) + kc/8 + c);
        }
        cpa_commit();
        cpa_wait<0>();
        __syncthreads();

        #pragma unroll
        for (int ks = 0; ks < 8; ks++) {
            unsigned a_h[4], a_l[4];
            unsigned aaddr = su + (unsigned)(arow*16 + ((2*ks+abit) ^ (arow&7)))*16;
            ldsm4(a_h, aaddr);
            ldsm4(a_l, aaddr + 16384u);
            unsigned bh_[2][4], bl_[2][4];
            #pragma unroll
            for (int np = 0; np < 2; np++) {
                int brow = ncol0 + np*16 + kb;
                unsigned baddr = su + 32768u + (unsigned)(brow*16 + ((2*ks+kbit) ^ (brow&7)))*16;
                ldsm4(bh_[np], baddr);
                ldsm4(bl_[np], baddr + 16384u);
            }
            #pragma unroll
            for (int np = 0; np < 2; np++) {
                mma16816(acc[2*np],   a_h, bh_[np]);
                mma16816(acc[2*np+1], a_h, bh_[np]+2);
            }
            #pragma unroll
            for (int np = 0; np < 2; np++) {
                mma16816(acc[2*np],   a_h, bl_[np]);
                mma16816(acc[2*np+1], a_h, bl_[np]+2);
            }
            #pragma unroll
            for (int np = 0; np < 2; np++) {
                mma16816(acc[2*np],   a_l, bh_[np]);
                mma16816(acc[2*np+1], a_l, bh_[np]+2);
            }
        }
    }

    #pragma unroll
    for (int nt = 0; nt < 4; nt++) {
        int n = n0 + ncol0 + nt*8 + 2*tig;
        float2 bb = *(const float2*)(bc + n);
        int ma = m0 + mrow0 + g;
        *(float2*)(out + (size_t)ma*128 + n) =
            make_float2(acc[nt][0] + bb.x, acc[nt][1] + bb.y);
        *(float2*)(out + (size_t)(ma+8)*128 + n) =
            make_float2(acc[nt][2] + bb.x, acc[nt][3] + bb.y);
    }
}

// ---------------------------------------------------------------------------
extern "C" void kernel_launch(void* const* d_in, const int* in_sizes, int n_in,
                              void* d_out, int out_size)
{
    const float* q    = (const float*)d_in[0];
    const float* k    = (const float*)d_in[1];
    const float* v    = (const float*)d_in[2];
    const float* mask = (const float*)d_in[3];
    const float* Wq   = (const float*)d_in[4];
    const float* Wk   = (const float*)d_in[5];
    const float* Wv   = (const float*)d_in[6];
    const float* Wc   = (const float*)d_in[7];
    const float* bc   = (const float*)d_in[8];
    float* out = (float*)d_out;

    const int qkv_smem  = 98304;
    const int attn_smem = 135168;
    const int outp_smem = 65536;

    cudaFuncSetAttribute(qkv_proj_kernel, cudaFuncAttributeMaxDynamicSharedMemorySize, qkv_smem);
    cudaFuncSetAttribute(attn_kernel, cudaFuncAttributeMaxDynamicSharedMemorySize, attn_smem);
    cudaFuncSetAttribute(out_proj_kernel, cudaFuncAttributeMaxDynamicSharedMemorySize, outp_smem);

    convert_kernel<<<dim3(96, 7), 256>>>(q, k, v, Wq, Wk, Wv, Wc);
    qkv_proj_kernel<<<dim3(8, 128, 3), 256, qkv_smem>>>();
    attn_kernel<<<dim3(8, 64), 256, attn_smem>>>(mask);
    out_proj_kernel<<<dim3(128, 2), 256, outp_smem>>>(bc, out);
}

// round 10
// speedup vs baseline: 2.3250x; 1.2437x over previous
#include <cuda_runtime.h>
#include <cuda_bf16.h>
#include <cuda_fp16.h>

#define BB 8
#define SS 1024
#define HH 8
#define DD 128
#define HD 1024

// ---- scratch planes (static device globals; 16-bit payload, type-punned) ----
__device__ __nv_bfloat16 g_Xqh[(size_t)BB*SS*128], g_Xql[(size_t)BB*SS*128];
__device__ __nv_bfloat16 g_Xkh[(size_t)BB*SS*128], g_Xkl[(size_t)BB*SS*128];
__device__ __nv_bfloat16 g_Xvh[(size_t)BB*SS*128], g_Xvl[(size_t)BB*SS*128];
__device__ __nv_bfloat16 g_Wqh[HD*128], g_Wql[HD*128];
__device__ __nv_bfloat16 g_Wkh[HD*128], g_Wkl[HD*128];
__device__ __nv_bfloat16 g_Wvh[HD*128], g_Wvl[HD*128];
__device__ __nv_bfloat16 g_Wch[128*HD], g_Wcl[128*HD];
__device__ __nv_bfloat16 g_Qh[(size_t)BB*HH*SS*DD];   // fp16 payload
__device__ __nv_bfloat16 g_Kh[(size_t)BB*HH*SS*DD];   // fp16 payload
__device__ __nv_bfloat16 g_Vh[(size_t)BB*HH*SS*DD];   // fp16 payload
__device__ __nv_bfloat16 g_Oh[(size_t)BB*SS*HD],   g_Ol[(size_t)BB*SS*HD];

// ---- helpers ----
__device__ __forceinline__ void mma16816(float* c, const unsigned* a, const unsigned* b) {
    asm volatile(
        "mma.sync.aligned.m16n8k16.row.col.f32.bf16.bf16.f32 "
        "{%0,%1,%2,%3}, {%4,%5,%6,%7}, {%8,%9}, {%0,%1,%2,%3};\n"
        : "+f"(c[0]), "+f"(c[1]), "+f"(c[2]), "+f"(c[3])
        : "r"(a[0]), "r"(a[1]), "r"(a[2]), "r"(a[3]), "r"(b[0]), "r"(b[1]));
}
__device__ __forceinline__ void mma16816h(float* c, const unsigned* a, const unsigned* b) {
    asm volatile(
        "mma.sync.aligned.m16n8k16.row.col.f32.f16.f16.f32 "
        "{%0,%1,%2,%3}, {%4,%5,%6,%7}, {%8,%9}, {%0,%1,%2,%3};\n"
        : "+f"(c[0]), "+f"(c[1]), "+f"(c[2]), "+f"(c[3])
        : "r"(a[0]), "r"(a[1]), "r"(a[2]), "r"(a[3]), "r"(b[0]), "r"(b[1]));
}
__device__ __forceinline__ void ldsm4(unsigned* r, unsigned addr) {
    asm volatile("ldmatrix.sync.aligned.m8n8.x4.shared.b16 {%0,%1,%2,%3}, [%4];"
        : "=r"(r[0]), "=r"(r[1]), "=r"(r[2]), "=r"(r[3]) : "r"(addr));
}
__device__ __forceinline__ void ldsm4t(unsigned* r, unsigned addr) {
    asm volatile("ldmatrix.sync.aligned.m8n8.x4.trans.shared.b16 {%0,%1,%2,%3}, [%4];"
        : "=r"(r[0]), "=r"(r[1]), "=r"(r[2]), "=r"(r[3]) : "r"(addr));
}
__device__ __forceinline__ unsigned cvt2(float hi, float lo) {
    unsigned r;
    asm("cvt.rn.bf16x2.f32 %0, %1, %2;" : "=r"(r) : "f"(hi), "f"(lo));
    return r;
}
__device__ __forceinline__ unsigned cvth2(float hi, float lo) {
    unsigned r;
    asm("cvt.rn.f16x2.f32 %0, %1, %2;" : "=r"(r) : "f"(hi), "f"(lo));
    return r;
}
__device__ __forceinline__ void packhl(float x0, float x1, unsigned& hi, unsigned& lo) {
    __nv_bfloat16 h0 = __float2bfloat16(x0), h1 = __float2bfloat16(x1);
    hi = ((unsigned)__bfloat16_as_ushort(h1) << 16) | (unsigned)__bfloat16_as_ushort(h0);
    lo = cvt2(x1 - __bfloat162float(h1), x0 - __bfloat162float(h0));
}
__device__ __forceinline__ void cpa(unsigned dst, const void* src) {
    asm volatile("cp.async.cg.shared.global [%0], [%1], 16;" :: "r"(dst), "l"(src));
}
__device__ __forceinline__ void cpa_commit() { asm volatile("cp.async.commit_group;"); }
template<int N> __device__ __forceinline__ void cpa_wait() {
    asm volatile("cp.async.wait_group %0;" :: "n"(N));
}

// ---------------------------------------------------------------------------
// Convert fp32 operands to bf16 hi/lo planes (one-time, memory-bound).
// ---------------------------------------------------------------------------
__global__ __launch_bounds__(256) void convert_kernel(
    const float* __restrict__ q, const float* __restrict__ k, const float* __restrict__ v,
    const float* __restrict__ Wq, const float* __restrict__ Wk, const float* __restrict__ Wv,
    const float* __restrict__ Wc)
{
    const float* src; __nv_bfloat16 *dh, *dl; int n4;
    switch (blockIdx.y) {
        case 0: src = q;  dh = g_Xqh; dl = g_Xql; n4 = BB*SS*128/4; break;
        case 1: src = k;  dh = g_Xkh; dl = g_Xkl; n4 = BB*SS*128/4; break;
        case 2: src = v;  dh = g_Xvh; dl = g_Xvl; n4 = BB*SS*128/4; break;
        case 3: src = Wq; dh = g_Wqh; dl = g_Wql; n4 = HD*128/4; break;
        case 4: src = Wk; dh = g_Wkh; dl = g_Wkl; n4 = HD*128/4; break;
        case 5: src = Wv; dh = g_Wvh; dl = g_Wvl; n4 = HD*128/4; break;
        default: src = Wc; dh = g_Wch; dl = g_Wcl; n4 = 128*HD/4; break;
    }
    for (int i = blockIdx.x*256 + threadIdx.x; i < n4; i += gridDim.x*256) {
        float4 f = ((const float4*)src)[i];
        unsigned h0,l0,h1,l1;
        packhl(f.x, f.y, h0, l0);
        packhl(f.z, f.w, h1, l1);
        ((uint2*)dh)[i] = make_uint2(h0, h1);
        ((uint2*)dl)[i] = make_uint2(l0, l1);
    }
}

// ---------------------------------------------------------------------------
// Fused QKV projection (validated r6 core). Epilogue: single fp16 plane out.
// ---------------------------------------------------------------------------
__global__ __launch_bounds__(256) void qkv_proj_kernel()
{
    extern __shared__ char smq[];
    const unsigned su = (unsigned)__cvta_generic_to_shared(smq);

    const uint4 *Xh4, *Xl4, *Wh4, *Wl4;
    __nv_bfloat16 *Oh;
    if (blockIdx.z == 0)      { Xh4=(const uint4*)g_Xqh; Xl4=(const uint4*)g_Xql;
                                Wh4=(const uint4*)g_Wqh; Wl4=(const uint4*)g_Wql;
                                Oh=g_Qh; }
    else if (blockIdx.z == 1) { Xh4=(const uint4*)g_Xkh; Xl4=(const uint4*)g_Xkl;
                                Wh4=(const uint4*)g_Wkh; Wl4=(const uint4*)g_Wkl;
                                Oh=g_Kh; }
    else                      { Xh4=(const uint4*)g_Xvh; Xl4=(const uint4*)g_Xvl;
                                Wh4=(const uint4*)g_Wvh; Wl4=(const uint4*)g_Wvl;
                                Oh=g_Vh; }

    const int m0 = blockIdx.y * 64;
    const int h  = blockIdx.x;
    const int tid = threadIdx.x;
    const int lane = tid & 31;
    const int wid  = tid >> 5;
    const int band = wid & 3, side = wid >> 2;
    const int g    = lane >> 2, tig = lane & 3;

    #pragma unroll
    for (int t = 0; t < 8; t++) {
        int idx = tid + 256*t;
        int pl = idx >> 10, i2 = idx & 1023;
        int r = i2 >> 4, c = i2 & 15;
        cpa(su + (unsigned)pl*16384u + (unsigned)(r*16 + (c^(r&7)))*16,
            (pl ? Xl4 : Xh4) + (size_t)(m0+r)*16 + c);
    }
    #pragma unroll
    for (int t = 0; t < 16; t++) {
        int idx = tid + 256*t;
        int pl = idx >> 11, i2 = idx & 2047;
        int r = i2 >> 4, c = i2 & 15;
        cpa(su + 32768u + (unsigned)pl*32768u + (unsigned)(r*16 + (c^(r&7)))*16,
            (pl ? Wl4 : Wh4) + (size_t)(h*128+r)*16 + c);
    }
    cpa_commit();
    cpa_wait<0>();
    __syncthreads();

    float acc[8][4];
    #pragma unroll
    for (int nt = 0; nt < 8; nt++)
        #pragma unroll
        for (int c = 0; c < 4; c++) acc[nt][c] = 0.f;

    const int arow = band*16 + (lane & 7) + ((lane >> 3) & 1)*8;
    const int abit = lane >> 4;
    const int kb   = (lane & 7) + ((lane >> 4) & 1)*8;
    const int kbit = (lane >> 3) & 1;

    #pragma unroll
    for (int ks = 0; ks < 8; ks++) {
        unsigned a_h[4], a_l[4];
        unsigned aaddr = su + (unsigned)(arow*16 + ((2*ks+abit) ^ (arow&7)))*16;
        ldsm4(a_h, aaddr);
        ldsm4(a_l, aaddr + 16384u);
        unsigned bh_[4][4], bl_[4][4];
        #pragma unroll
        for (int np = 0; np < 4; np++) {
            int brow = side*64 + np*16 + kb;
            unsigned baddr = su + 32768u + (unsigned)(brow*16 + ((2*ks+kbit) ^ (brow&7)))*16;
            ldsm4(bh_[np], baddr);
            ldsm4(bl_[np], baddr + 32768u);
        }
        #pragma unroll
        for (int np = 0; np < 4; np++) {
            mma16816(acc[2*np],   a_h, bh_[np]);
            mma16816(acc[2*np+1], a_h, bh_[np]+2);
        }
        #pragma unroll
        for (int np = 0; np < 4; np++) {
            mma16816(acc[2*np],   a_h, bl_[np]);
            mma16816(acc[2*np+1], a_h, bl_[np]+2);
        }
        #pragma unroll
        for (int np = 0; np < 4; np++) {
            mma16816(acc[2*np],   a_l, bh_[np]);
            mma16816(acc[2*np+1], a_l, bh_[np]+2);
        }
    }

    // epilogue: single fp16 plane at [B,H,S,D]
    #pragma unroll
    for (int nt = 0; nt < 8; nt++) {
        int col = side*64 + nt*8 + 2*tig;
        int ma = m0 + band*16 + g;
        int mb2 = ma + 8;
        size_t offa = (((size_t)((ma  >> 10)*HH + h))*SS + (ma  & 1023))*DD + col;
        size_t offb = (((size_t)((mb2 >> 10)*HH + h))*SS + (mb2 & 1023))*DD + col;
        *(unsigned*)(Oh + offa) = cvth2(acc[nt][1], acc[nt][0]);
        *(unsigned*)(Oh + offb) = cvth2(acc[nt][3], acc[nt][2]);
    }
}

// ---------------------------------------------------------------------------
// Flash attention (r6/r9 structure): QK single fp16, PV single fp16.
// 256 thr / 8 warps, cp.async double-buffered K/V, 2 CTAs/SM.
// smem: msk 0 (4KB), Qh 4096 (32KB), KV0 36864 (32KB: Kh+0, Vh+16384),
//       KV1 69632 (32KB). Total 100KB.
// ---------------------------------------------------------------------------
__global__ __launch_bounds__(256, 2) void attn_kernel(const float* __restrict__ mask)
{
    extern __shared__ char sm[];
    float* msk_s = (float*)sm;
    const unsigned smem_u = (unsigned)__cvta_generic_to_shared(sm);
    const unsigned offQh = 4096u, KV0 = 36864u, KV1 = 69632u;

    const int tid  = threadIdx.x;
    const int lane = tid & 31;
    const int wid  = tid >> 5;
    const int wq0  = wid * 16;
    const int g    = lane >> 2;
    const int tig  = lane & 3;

    const int bh = blockIdx.y;
    const int b_ = bh >> 3, h = bh & 7;
    const int q0 = blockIdx.x * 128;

    const uint4* qh4 = (const uint4*)(g_Qh + ((size_t)bh*SS + q0)*DD);
    const uint4* kh4 = (const uint4*)(g_Kh + (size_t)bh*SS*DD);
    const uint4* vh4 = (const uint4*)(g_Vh + (size_t)bh*SS*DD);
    const float* mb = mask + b_*SS;

    // mask (1024 floats) + Qh plane
    *(float4*)&msk_s[tid*4] = ((const float4*)mb)[tid];
    #pragma unroll
    for (int t = 0; t < 8; t++) {
        int idx = tid + 256*t;
        int r = idx >> 4, c = idx & 15;
        unsigned phys = (unsigned)(r*16 + (c ^ (r&7)))*16;
        *(uint4*)(sm + 4096 + phys) = qh4[idx];
    }
    // prefetch KV block 0 into buf0
    {
        #pragma unroll
        for (int t = 0; t < 4; t++) {
            int idx = tid + 256*t;
            int r = idx >> 4, c = idx & 15;
            unsigned dst = smem_u + KV0 + (unsigned)(r*16 + (c^(r&7)))*16;
            cpa(dst,          kh4 + idx);
            cpa(dst + 16384u, vh4 + idx);
        }
        cpa_commit();
    }

    float o[16][4];
    #pragma unroll
    for (int nt = 0; nt < 16; nt++)
        #pragma unroll
        for (int c = 0; c < 4; c++) o[nt][c] = 0.f;

    float m0s = -3.0e38f, m1s = -3.0e38f, l0s = 0.f, l1s = 0.f;
    const float scale = 0.08838834764831845f;  // 1/sqrt(128)

    const int arow = wq0 + (lane & 7) + ((lane >> 3) & 1)*8;
    const int abit = lane >> 4;
    const int kbr  = (lane & 7) + ((lane >> 4) & 1)*8;
    const int kbit = (lane >> 3) & 1;
    const int vr   = (lane & 7) + ((lane >> 3) & 1)*8;
    const int vbit = (lane >> 4) & 1;

    for (int it = 0; it < 16; it++) {
        const int j0 = it*64;
        const unsigned kvcur = (it & 1) ? KV1 : KV0;
        if (it < 15) {
            const unsigned kvnxt = (it & 1) ? KV0 : KV1;
            #pragma unroll
            for (int t = 0; t < 4; t++) {
                int idx = tid + 256*t;
                int r = idx >> 4, c = idx & 15;
                unsigned dst = smem_u + kvnxt + (unsigned)(r*16 + (c^(r&7)))*16;
                int gi = (j0 + 64 + r)*16 + c;
                cpa(dst,          kh4 + gi);
                cpa(dst + 16384u, vh4 + gi);
            }
            cpa_commit();
            cpa_wait<1>();
        } else {
            cpa_wait<0>();
        }
        __syncthreads();

        // ---- S = Q K^T (single-term fp16) ----
        float sacc[8][4];
        #pragma unroll
        for (int nt = 0; nt < 8; nt++)
            #pragma unroll
            for (int c = 0; c < 4; c++) sacc[nt][c] = 0.f;

        #pragma unroll
        for (int ks = 0; ks < 8; ks++) {
            unsigned a_h[4];
            unsigned aaddr = smem_u + offQh + (unsigned)(arow*16 + ((2*ks+abit) ^ (arow&7)))*16;
            ldsm4(a_h, aaddr);
            unsigned bh_[4][4];
            #pragma unroll
            for (int np = 0; np < 4; np++) {
                int brow = np*16 + kbr;
                unsigned baddr = smem_u + kvcur + (unsigned)(brow*16 + ((2*ks+kbit) ^ (brow&7)))*16;
                ldsm4(bh_[np], baddr);
            }
            #pragma unroll
            for (int np = 0; np < 4; np++) {
                mma16816h(sacc[2*np],   a_h, bh_[np]);
                mma16816h(sacc[2*np+1], a_h, bh_[np]+2);
            }
        }

        // ---- online softmax (identical r4/r6/r9) ----
        float mx0 = -3.0e38f, mx1 = -3.0e38f;
        #pragma unroll
        for (int nt = 0; nt < 8; nt++) {
            float2 mk = *(float2*)&msk_s[j0 + nt*8 + 2*tig];
            sacc[nt][0] = sacc[nt][0]*scale + mk.x;
            sacc[nt][1] = sacc[nt][1]*scale + mk.y;
            sacc[nt][2] = sacc[nt][2]*scale + mk.x;
            sacc[nt][3] = sacc[nt][3]*scale + mk.y;
            mx0 = fmaxf(mx0, fmaxf(sacc[nt][0], sacc[nt][1]));
            mx1 = fmaxf(mx1, fmaxf(sacc[nt][2], sacc[nt][3]));
        }
        #pragma unroll
        for (int mskb = 1; mskb <= 2; mskb <<= 1) {
            mx0 = fmaxf(mx0, __shfl_xor_sync(0xffffffffu, mx0, mskb));
            mx1 = fmaxf(mx1, __shfl_xor_sync(0xffffffffu, mx1, mskb));
        }
        float mn0 = fmaxf(m0s, mx0), mn1 = fmaxf(m1s, mx1);
        float al0 = __expf(m0s - mn0), al1 = __expf(m1s - mn1);
        m0s = mn0; m1s = mn1;

        float sum0 = 0.f, sum1 = 0.f;
        #pragma unroll
        for (int nt = 0; nt < 8; nt++) {
            float p0 = __expf(sacc[nt][0] - mn0);
            float p1 = __expf(sacc[nt][1] - mn0);
            float p2 = __expf(sacc[nt][2] - mn1);
            float p3 = __expf(sacc[nt][3] - mn1);
            sacc[nt][0] = p0; sacc[nt][1] = p1; sacc[nt][2] = p2; sacc[nt][3] = p3;
            sum0 += p0 + p1; sum1 += p2 + p3;
        }
        #pragma unroll
        for (int mskb = 1; mskb <= 2; mskb <<= 1) {
            sum0 += __shfl_xor_sync(0xffffffffu, sum0, mskb);
            sum1 += __shfl_xor_sync(0xffffffffu, sum1, mskb);
        }
        l0s = l0s*al0 + sum0;
        l1s = l1s*al1 + sum1;

        #pragma unroll
        for (int nt = 0; nt < 16; nt++) {
            o[nt][0] *= al0; o[nt][1] *= al0;
            o[nt][2] *= al1; o[nt][3] *= al1;
        }

        // ---- O += P V (fp16 single-term) ----
        #pragma unroll
        for (int kk = 0; kk < 4; kk++) {
            unsigned pah[4];
            #pragma unroll
            for (int half = 0; half < 2; half++) {
                int nt = 2*kk + half;
                pah[2*half]   = cvth2(sacc[nt][1], sacc[nt][0]);
                pah[2*half+1] = cvth2(sacc[nt][3], sacc[nt][2]);
            }
            int vrow = kk*16 + vr;
            #pragma unroll
            for (int np = 0; np < 8; np++) {
                int vchk = 2*np + vbit;
                unsigned vaddr = smem_u + kvcur + 16384u
                               + (unsigned)(vrow*16 + (vchk ^ (vrow&7)))*16;
                unsigned vbh[4];
                ldsm4t(vbh, vaddr);
                mma16816h(o[2*np],   pah, vbh);
                mma16816h(o[2*np+1], pah, vbh+2);
            }
        }
        __syncthreads();
    }

    // epilogue: normalize, write hi/lo bf16 planes of O (concat [B,S,H*D])
    float inv0 = 1.f / (l0s + 1e-12f);
    float inv1 = 1.f / (l1s + 1e-12f);
    int r0 = q0 + wq0 + g;
    size_t base0 = ((size_t)(b_*SS + r0))*HD + h*DD;
    size_t base1 = base0 + (size_t)8*HD;
    #pragma unroll
    for (int nt = 0; nt < 16; nt++) {
        int cc = nt*8 + 2*tig;
        unsigned hi, lo;
        packhl(o[nt][0]*inv0, o[nt][1]*inv0, hi, lo);
        *(unsigned*)(g_Oh + base0 + cc) = hi;
        *(unsigned*)(g_Ol + base0 + cc) = lo;
        packhl(o[nt][2]*inv1, o[nt][3]*inv1, hi, lo);
        *(unsigned*)(g_Oh + base1 + cc) = hi;
        *(unsigned*)(g_Ol + base1 + cc) = lo;
    }
}

// ---------------------------------------------------------------------------
// Output projection (validated r7): bf16 hi/lo mma.sync, 64x64 tiles, grid 256.
// ---------------------------------------------------------------------------
__global__ __launch_bounds__(256) void out_proj_kernel(
    const float* __restrict__ bc, float* __restrict__ out)
{
    extern __shared__ char smo[];
    const unsigned su = (unsigned)__cvta_generic_to_shared(smo);

    const int m0 = blockIdx.x * 64;
    const int n0 = blockIdx.y * 64;
    const int tid = threadIdx.x;
    const int lane = tid & 31;
    const int wid  = tid >> 5;
    const int mrow0 = (wid & 3)*16;
    const int ncol0 = (wid >> 2)*32;
    const int g = lane >> 2, tig = lane & 3;

    const int arow = mrow0 + (lane & 7) + ((lane >> 3) & 1)*8;
    const int abit = lane >> 4;
    const int kb   = (lane & 7) + ((lane >> 4) & 1)*8;
    const int kbit = (lane >> 3) & 1;

    float acc[4][4];
    #pragma unroll
    for (int nt = 0; nt < 4; nt++)
        #pragma unroll
        for (int c = 0; c < 4; c++) acc[nt][c] = 0.f;

    const uint4* Ah4 = (const uint4*)g_Oh;
    const uint4* Al4 = (const uint4*)g_Ol;
    const uint4* Bh4 = (const uint4*)g_Wch;
    const uint4* Bl4 = (const uint4*)g_Wcl;

    for (int kc = 0; kc < HD; kc += 128) {
        __syncthreads();
        #pragma unroll
        for (int t = 0; t < 8; t++) {
            int idx = tid + 256*t;
            int pl = idx >> 10, i2 = idx & 1023;
            int r = i2 >> 4, c = i2 & 15;
            cpa(su + (unsigned)pl*16384u + (unsigned)(r*16 + (c^(r&7)))*16,
                (pl ? Al4 : Ah4) + (size_t)(m0+r)*(HD/8) + kc/8 + c);
        }
        #pragma unroll
        for (int t = 0; t < 8; t++) {
            int idx = tid + 256*t;
            int pl = idx >> 10, i2 = idx & 1023;
            int r = i2 >> 4, c = i2 & 15;
            cpa(su + 32768u + (unsigned)pl*16384u + (unsigned)(r*16 + (c^(r&7)))*16,
                (pl ? Bl4 : Bh4) + (size_t)(n0+r)*(HD/8) + kc/8 + c);
        }
        cpa_commit();
        cpa_wait<0>();
        __syncthreads();

        #pragma unroll
        for (int ks = 0; ks < 8; ks++) {
            unsigned a_h[4], a_l[4];
            unsigned aaddr = su + (unsigned)(arow*16 + ((2*ks+abit) ^ (arow&7)))*16;
            ldsm4(a_h, aaddr);
            ldsm4(a_l, aaddr + 16384u);
            unsigned bh_[2][4], bl_[2][4];
            #pragma unroll
            for (int np = 0; np < 2; np++) {
                int brow = ncol0 + np*16 + kb;
                unsigned baddr = su + 32768u + (unsigned)(brow*16 + ((2*ks+kbit) ^ (brow&7)))*16;
                ldsm4(bh_[np], baddr);
                ldsm4(bl_[np], baddr + 16384u);
            }
            #pragma unroll
            for (int np = 0; np < 2; np++) {
                mma16816(acc[2*np],   a_h, bh_[np]);
                mma16816(acc[2*np+1], a_h, bh_[np]+2);
            }
            #pragma unroll
            for (int np = 0; np < 2; np++) {
                mma16816(acc[2*np],   a_h, bl_[np]);
                mma16816(acc[2*np+1], a_h, bl_[np]+2);
            }
            #pragma unroll
            for (int np = 0; np < 2; np++) {
                mma16816(acc[2*np],   a_l, bh_[np]);
                mma16816(acc[2*np+1], a_l, bh_[np]+2);
            }
        }
    }

    #pragma unroll
    for (int nt = 0; nt < 4; nt++) {
        int n = n0 + ncol0 + nt*8 + 2*tig;
        float2 bb = *(const float2*)(bc + n);
        int ma = m0 + mrow0 + g;
        *(float2*)(out + (size_t)ma*128 + n) =
            make_float2(acc[nt][0] + bb.x, acc[nt][1] + bb.y);
        *(float2*)(out + (size_t)(ma+8)*128 + n) =
            make_float2(acc[nt][2] + bb.x, acc[nt][3] + bb.y);
    }
}

// ---------------------------------------------------------------------------
extern "C" void kernel_launch(void* const* d_in, const int* in_sizes, int n_in,
                              void* d_out, int out_size)
{
    const float* q    = (const float*)d_in[0];
    const float* k    = (const float*)d_in[1];
    const float* v    = (const float*)d_in[2];
    const float* mask = (const float*)d_in[3];
    const float* Wq   = (const float*)d_in[4];
    const float* Wk   = (const float*)d_in[5];
    const float* Wv   = (const float*)d_in[6];
    const float* Wc   = (const float*)d_in[7];
    const float* bc   = (const float*)d_in[8];
    float* out = (float*)d_out;

    const int qkv_smem  = 98304;
    const int attn_smem = 102400;
    const int outp_smem = 65536;

    cudaFuncSetAttribute(qkv_proj_kernel, cudaFuncAttributeMaxDynamicSharedMemorySize, qkv_smem);
    cudaFuncSetAttribute(attn_kernel, cudaFuncAttributeMaxDynamicSharedMemorySize, attn_smem);
    cudaFuncSetAttribute(out_proj_kernel, cudaFuncAttributeMaxDynamicSharedMemorySize, outp_smem);

    convert_kernel<<<dim3(96, 7), 256>>>(q, k, v, Wq, Wk, Wv, Wc);
    qkv_proj_kernel<<<dim3(8, 128, 3), 256, qkv_smem>>>();
    attn_kernel<<<dim3(8, 64), 256, attn_smem>>>(mask);
    out_proj_kernel<<<dim3(128, 2), 256, outp_smem>>>(bc, out);
}

// round 11
// speedup vs baseline: 2.8192x; 1.2126x over previous
#include <cuda_runtime.h>
#include <cuda_bf16.h>
#include <cuda_fp16.h>

#define BB 8
#define SS 1024
#define HH 8
#define DD 128
#define HD 1024

// ---- scratch planes (fp16 payload throughout) ----
__device__ __half g_Xq[(size_t)BB*SS*128];
__device__ __half g_Xk[(size_t)BB*SS*128];
__device__ __half g_Xv[(size_t)BB*SS*128];
__device__ __half g_Wq[HD*128], g_Wk[HD*128], g_Wv[HD*128];
__device__ __half g_Wc[128*HD];
__device__ __half g_Q[(size_t)BB*HH*SS*DD];
__device__ __half g_K[(size_t)BB*HH*SS*DD];
__device__ __half g_V[(size_t)BB*HH*SS*DD];
__device__ __half g_O[(size_t)BB*SS*HD];

// ---- helpers ----
__device__ __forceinline__ void mma16816h(float* c, const unsigned* a, const unsigned* b) {
    asm volatile(
        "mma.sync.aligned.m16n8k16.row.col.f32.f16.f16.f32 "
        "{%0,%1,%2,%3}, {%4,%5,%6,%7}, {%8,%9}, {%0,%1,%2,%3};\n"
        : "+f"(c[0]), "+f"(c[1]), "+f"(c[2]), "+f"(c[3])
        : "r"(a[0]), "r"(a[1]), "r"(a[2]), "r"(a[3]), "r"(b[0]), "r"(b[1]));
}
__device__ __forceinline__ void ldsm4(unsigned* r, unsigned addr) {
    asm volatile("ldmatrix.sync.aligned.m8n8.x4.shared.b16 {%0,%1,%2,%3}, [%4];"
        : "=r"(r[0]), "=r"(r[1]), "=r"(r[2]), "=r"(r[3]) : "r"(addr));
}
__device__ __forceinline__ void ldsm4t(unsigned* r, unsigned addr) {
    asm volatile("ldmatrix.sync.aligned.m8n8.x4.trans.shared.b16 {%0,%1,%2,%3}, [%4];"
        : "=r"(r[0]), "=r"(r[1]), "=r"(r[2]), "=r"(r[3]) : "r"(addr));
}
__device__ __forceinline__ unsigned cvth2(float hi, float lo) {
    unsigned r;
    asm("cvt.rn.f16x2.f32 %0, %1, %2;" : "=r"(r) : "f"(hi), "f"(lo));
    return r;
}
__device__ __forceinline__ void cpa(unsigned dst, const void* src) {
    asm volatile("cp.async.cg.shared.global [%0], [%1], 16;" :: "r"(dst), "l"(src));
}
__device__ __forceinline__ void cpa_commit() { asm volatile("cp.async.commit_group;"); }
template<int N> __device__ __forceinline__ void cpa_wait() {
    asm volatile("cp.async.wait_group %0;" :: "n"(N));
}

// ---------------------------------------------------------------------------
// Convert fp32 operands to single fp16 planes (one-time, memory-bound).
// ---------------------------------------------------------------------------
__global__ __launch_bounds__(256) void convert_kernel(
    const float* __restrict__ q, const float* __restrict__ k, const float* __restrict__ v,
    const float* __restrict__ Wq, const float* __restrict__ Wk, const float* __restrict__ Wv,
    const float* __restrict__ Wc)
{
    const float* src; __half* dh; int n4;
    switch (blockIdx.y) {
        case 0: src = q;  dh = g_Xq; n4 = BB*SS*128/4; break;
        case 1: src = k;  dh = g_Xk; n4 = BB*SS*128/4; break;
        case 2: src = v;  dh = g_Xv; n4 = BB*SS*128/4; break;
        case 3: src = Wq; dh = g_Wq; n4 = HD*128/4; break;
        case 4: src = Wk; dh = g_Wk; n4 = HD*128/4; break;
        case 5: src = Wv; dh = g_Wv; n4 = HD*128/4; break;
        default: src = Wc; dh = g_Wc; n4 = 128*HD/4; break;
    }
    for (int i = blockIdx.x*256 + threadIdx.x; i < n4; i += gridDim.x*256) {
        float4 f = ((const float4*)src)[i];
        ((uint2*)dh)[i] = make_uint2(cvth2(f.y, f.x), cvth2(f.w, f.z));
    }
}

// ---------------------------------------------------------------------------
// Fused QKV projection: single-term fp16 mma.sync.
// CTA tile 64(M) x 128(N=head), K=128. 256 thr, 8 warps.
// smem: A 0 (16KB), B 16384 (32KB) -> 48KB.
// ---------------------------------------------------------------------------
__global__ __launch_bounds__(256) void qkv_proj_kernel()
{
    extern __shared__ char smq[];
    const unsigned su = (unsigned)__cvta_generic_to_shared(smq);

    const uint4 *Xp, *Wp;
    __half* Oh;
    if (blockIdx.z == 0)      { Xp=(const uint4*)g_Xq; Wp=(const uint4*)g_Wq; Oh=g_Q; }
    else if (blockIdx.z == 1) { Xp=(const uint4*)g_Xk; Wp=(const uint4*)g_Wk; Oh=g_K; }
    else                      { Xp=(const uint4*)g_Xv; Wp=(const uint4*)g_Wv; Oh=g_V; }

    const int m0 = blockIdx.y * 64;
    const int h  = blockIdx.x;
    const int tid = threadIdx.x;
    const int lane = tid & 31;
    const int wid  = tid >> 5;
    const int band = wid & 3, side = wid >> 2;
    const int g    = lane >> 2, tig = lane & 3;

    #pragma unroll
    for (int t = 0; t < 4; t++) {
        int idx = tid + 256*t;
        int r = idx >> 4, c = idx & 15;
        cpa(su + (unsigned)(r*16 + (c^(r&7)))*16, Xp + (size_t)(m0+r)*16 + c);
    }
    #pragma unroll
    for (int t = 0; t < 8; t++) {
        int idx = tid + 256*t;
        int r = idx >> 4, c = idx & 15;
        cpa(su + 16384u + (unsigned)(r*16 + (c^(r&7)))*16, Wp + (size_t)(h*128+r)*16 + c);
    }
    cpa_commit();
    cpa_wait<0>();
    __syncthreads();

    float acc[8][4];
    #pragma unroll
    for (int nt = 0; nt < 8; nt++)
        #pragma unroll
        for (int c = 0; c < 4; c++) acc[nt][c] = 0.f;

    const int arow = band*16 + (lane & 7) + ((lane >> 3) & 1)*8;
    const int abit = lane >> 4;
    const int kb   = (lane & 7) + ((lane >> 4) & 1)*8;
    const int kbit = (lane >> 3) & 1;

    #pragma unroll
    for (int ks = 0; ks < 8; ks++) {
        unsigned a_h[4];
        unsigned aaddr = su + (unsigned)(arow*16 + ((2*ks+abit) ^ (arow&7)))*16;
        ldsm4(a_h, aaddr);
        unsigned bh_[4][4];
        #pragma unroll
        for (int np = 0; np < 4; np++) {
            int brow = side*64 + np*16 + kb;
            unsigned baddr = su + 16384u + (unsigned)(brow*16 + ((2*ks+kbit) ^ (brow&7)))*16;
            ldsm4(bh_[np], baddr);
        }
        #pragma unroll
        for (int np = 0; np < 4; np++) {
            mma16816h(acc[2*np],   a_h, bh_[np]);
            mma16816h(acc[2*np+1], a_h, bh_[np]+2);
        }
    }

    // epilogue: single fp16 plane at [B,H,S,D]
    #pragma unroll
    for (int nt = 0; nt < 8; nt++) {
        int col = side*64 + nt*8 + 2*tig;
        int ma = m0 + band*16 + g;
        int mb2 = ma + 8;
        size_t offa = (((size_t)((ma  >> 10)*HH + h))*SS + (ma  & 1023))*DD + col;
        size_t offb = (((size_t)((mb2 >> 10)*HH + h))*SS + (mb2 & 1023))*DD + col;
        *(unsigned*)(Oh + offa) = cvth2(acc[nt][1], acc[nt][0]);
        *(unsigned*)(Oh + offb) = cvth2(acc[nt][3], acc[nt][2]);
    }
}

// ---------------------------------------------------------------------------
// Flash attention (validated r10 structure): QK single fp16, PV single fp16.
// 256 thr / 8 warps, cp.async double-buffered K/V, 2 CTAs/SM.
// smem: msk 0 (4KB), Q 4096 (32KB), KV0 36864 (32KB: K+0, V+16384),
//       KV1 69632 (32KB). Total 100KB.
// Epilogue: O single fp16 plane.
// ---------------------------------------------------------------------------
__global__ __launch_bounds__(256, 2) void attn_kernel(const float* __restrict__ mask)
{
    extern __shared__ char sm[];
    float* msk_s = (float*)sm;
    const unsigned smem_u = (unsigned)__cvta_generic_to_shared(sm);
    const unsigned offQh = 4096u, KV0 = 36864u, KV1 = 69632u;

    const int tid  = threadIdx.x;
    const int lane = tid & 31;
    const int wid  = tid >> 5;
    const int wq0  = wid * 16;
    const int g    = lane >> 2;
    const int tig  = lane & 3;

    const int bh = blockIdx.y;
    const int b_ = bh >> 3, h = bh & 7;
    const int q0 = blockIdx.x * 128;

    const uint4* qh4 = (const uint4*)(g_Q + ((size_t)bh*SS + q0)*DD);
    const uint4* kh4 = (const uint4*)(g_K + (size_t)bh*SS*DD);
    const uint4* vh4 = (const uint4*)(g_V + (size_t)bh*SS*DD);
    const float* mb = mask + b_*SS;

    // mask (1024 floats) + Q plane
    *(float4*)&msk_s[tid*4] = ((const float4*)mb)[tid];
    #pragma unroll
    for (int t = 0; t < 8; t++) {
        int idx = tid + 256*t;
        int r = idx >> 4, c = idx & 15;
        unsigned phys = (unsigned)(r*16 + (c ^ (r&7)))*16;
        *(uint4*)(sm + 4096 + phys) = qh4[idx];
    }
    // prefetch KV block 0 into buf0
    {
        #pragma unroll
        for (int t = 0; t < 4; t++) {
            int idx = tid + 256*t;
            int r = idx >> 4, c = idx & 15;
            unsigned dst = smem_u + KV0 + (unsigned)(r*16 + (c^(r&7)))*16;
            cpa(dst,          kh4 + idx);
            cpa(dst + 16384u, vh4 + idx);
        }
        cpa_commit();
    }

    float o[16][4];
    #pragma unroll
    for (int nt = 0; nt < 16; nt++)
        #pragma unroll
        for (int c = 0; c < 4; c++) o[nt][c] = 0.f;

    float m0s = -3.0e38f, m1s = -3.0e38f, l0s = 0.f, l1s = 0.f;
    const float scale = 0.08838834764831845f;  // 1/sqrt(128)

    const int arow = wq0 + (lane & 7) + ((lane >> 3) & 1)*8;
    const int abit = lane >> 4;
    const int kbr  = (lane & 7) + ((lane >> 4) & 1)*8;
    const int kbit = (lane >> 3) & 1;
    const int vr   = (lane & 7) + ((lane >> 3) & 1)*8;
    const int vbit = (lane >> 4) & 1;

    for (int it = 0; it < 16; it++) {
        const int j0 = it*64;
        const unsigned kvcur = (it & 1) ? KV1 : KV0;
        if (it < 15) {
            const unsigned kvnxt = (it & 1) ? KV0 : KV1;
            #pragma unroll
            for (int t = 0; t < 4; t++) {
                int idx = tid + 256*t;
                int r = idx >> 4, c = idx & 15;
                unsigned dst = smem_u + kvnxt + (unsigned)(r*16 + (c^(r&7)))*16;
                int gi = (j0 + 64 + r)*16 + c;
                cpa(dst,          kh4 + gi);
                cpa(dst + 16384u, vh4 + gi);
            }
            cpa_commit();
            cpa_wait<1>();
        } else {
            cpa_wait<0>();
        }
        __syncthreads();

        // ---- S = Q K^T (single-term fp16) ----
        float sacc[8][4];
        #pragma unroll
        for (int nt = 0; nt < 8; nt++)
            #pragma unroll
            for (int c = 0; c < 4; c++) sacc[nt][c] = 0.f;

        #pragma unroll
        for (int ks = 0; ks < 8; ks++) {
            unsigned a_h[4];
            unsigned aaddr = smem_u + offQh + (unsigned)(arow*16 + ((2*ks+abit) ^ (arow&7)))*16;
            ldsm4(a_h, aaddr);
            unsigned bh_[4][4];
            #pragma unroll
            for (int np = 0; np < 4; np++) {
                int brow = np*16 + kbr;
                unsigned baddr = smem_u + kvcur + (unsigned)(brow*16 + ((2*ks+kbit) ^ (brow&7)))*16;
                ldsm4(bh_[np], baddr);
            }
            #pragma unroll
            for (int np = 0; np < 4; np++) {
                mma16816h(sacc[2*np],   a_h, bh_[np]);
                mma16816h(sacc[2*np+1], a_h, bh_[np]+2);
            }
        }

        // ---- online softmax (validated r4/r6/r9/r10) ----
        float mx0 = -3.0e38f, mx1 = -3.0e38f;
        #pragma unroll
        for (int nt = 0; nt < 8; nt++) {
            float2 mk = *(float2*)&msk_s[j0 + nt*8 + 2*tig];
            sacc[nt][0] = sacc[nt][0]*scale + mk.x;
            sacc[nt][1] = sacc[nt][1]*scale + mk.y;
            sacc[nt][2] = sacc[nt][2]*scale + mk.x;
            sacc[nt][3] = sacc[nt][3]*scale + mk.y;
            mx0 = fmaxf(mx0, fmaxf(sacc[nt][0], sacc[nt][1]));
            mx1 = fmaxf(mx1, fmaxf(sacc[nt][2], sacc[nt][3]));
        }
        #pragma unroll
        for (int mskb = 1; mskb <= 2; mskb <<= 1) {
            mx0 = fmaxf(mx0, __shfl_xor_sync(0xffffffffu, mx0, mskb));
            mx1 = fmaxf(mx1, __shfl_xor_sync(0xffffffffu, mx1, mskb));
        }
        float mn0 = fmaxf(m0s, mx0), mn1 = fmaxf(m1s, mx1);
        float al0 = __expf(m0s - mn0), al1 = __expf(m1s - mn1);
        m0s = mn0; m1s = mn1;

        float sum0 = 0.f, sum1 = 0.f;
        #pragma unroll
        for (int nt = 0; nt < 8; nt++) {
            float p0 = __expf(sacc[nt][0] - mn0);
            float p1 = __expf(sacc[nt][1] - mn0);
            float p2 = __expf(sacc[nt][2] - mn1);
            float p3 = __expf(sacc[nt][3] - mn1);
            sacc[nt][0] = p0; sacc[nt][1] = p1; sacc[nt][2] = p2; sacc[nt][3] = p3;
            sum0 += p0 + p1; sum1 += p2 + p3;
        }
        #pragma unroll
        for (int mskb = 1; mskb <= 2; mskb <<= 1) {
            sum0 += __shfl_xor_sync(0xffffffffu, sum0, mskb);
            sum1 += __shfl_xor_sync(0xffffffffu, sum1, mskb);
        }
        l0s = l0s*al0 + sum0;
        l1s = l1s*al1 + sum1;

        #pragma unroll
        for (int nt = 0; nt < 16; nt++) {
            o[nt][0] *= al0; o[nt][1] *= al0;
            o[nt][2] *= al1; o[nt][3] *= al1;
        }

        // ---- O += P V (fp16 single-term) ----
        #pragma unroll
        for (int kk = 0; kk < 4; kk++) {
            unsigned pah[4];
            #pragma unroll
            for (int half = 0; half < 2; half++) {
                int nt = 2*kk + half;
                pah[2*half]   = cvth2(sacc[nt][1], sacc[nt][0]);
                pah[2*half+1] = cvth2(sacc[nt][3], sacc[nt][2]);
            }
            int vrow = kk*16 + vr;
            #pragma unroll
            for (int np = 0; np < 8; np++) {
                int vchk = 2*np + vbit;
                unsigned vaddr = smem_u + kvcur + 16384u
                               + (unsigned)(vrow*16 + (vchk ^ (vrow&7)))*16;
                unsigned vbh[4];
                ldsm4t(vbh, vaddr);
                mma16816h(o[2*np],   pah, vbh);
                mma16816h(o[2*np+1], pah, vbh+2);
            }
        }
        __syncthreads();
    }

    // epilogue: normalize, write single fp16 plane of O (concat [B,S,H*D])
    float inv0 = 1.f / (l0s + 1e-12f);
    float inv1 = 1.f / (l1s + 1e-12f);
    int r0 = q0 + wq0 + g;
    size_t base0 = ((size_t)(b_*SS + r0))*HD + h*DD;
    size_t base1 = base0 + (size_t)8*HD;
    #pragma unroll
    for (int nt = 0; nt < 16; nt++) {
        int cc = nt*8 + 2*tig;
        *(unsigned*)(g_O + base0 + cc) = cvth2(o[nt][1]*inv0, o[nt][0]*inv0);
        *(unsigned*)(g_O + base1 + cc) = cvth2(o[nt][3]*inv1, o[nt][2]*inv1);
    }
}

// ---------------------------------------------------------------------------
// Output projection: single-term fp16 mma.sync, 64x64 tiles, grid (128,2).
// smem: A 0 (16KB), B 16384 (16KB) -> 32KB.
// ---------------------------------------------------------------------------
__global__ __launch_bounds__(256) void out_proj_kernel(
    const float* __restrict__ bc, float* __restrict__ out)
{
    extern __shared__ char smo[];
    const unsigned su = (unsigned)__cvta_generic_to_shared(smo);

    const int m0 = blockIdx.x * 64;
    const int n0 = blockIdx.y * 64;
    const int tid = threadIdx.x;
    const int lane = tid & 31;
    const int wid  = tid >> 5;
    const int mrow0 = (wid & 3)*16;
    const int ncol0 = (wid >> 2)*32;
    const int g = lane >> 2, tig = lane & 3;

    const int arow = mrow0 + (lane & 7) + ((lane >> 3) & 1)*8;
    const int abit = lane >> 4;
    const int kb   = (lane & 7) + ((lane >> 4) & 1)*8;
    const int kbit = (lane >> 3) & 1;

    float acc[4][4];
    #pragma unroll
    for (int nt = 0; nt < 4; nt++)
        #pragma unroll
        for (int c = 0; c < 4; c++) acc[nt][c] = 0.f;

    const uint4* Ap = (const uint4*)g_O;
    const uint4* Bp = (const uint4*)g_Wc;

    for (int kc = 0; kc < HD; kc += 128) {
        __syncthreads();
        #pragma unroll
        for (int t = 0; t < 4; t++) {
            int idx = tid + 256*t;
            int r = idx >> 4, c = idx & 15;
            cpa(su + (unsigned)(r*16 + (c^(r&7)))*16,
                Ap + (size_t)(m0+r)*(HD/8) + kc/8 + c);
        }
        #pragma unroll
        for (int t = 0; t < 4; t++) {
            int idx = tid + 256*t;
            int r = idx >> 4, c = idx & 15;
            cpa(su + 16384u + (unsigned)(r*16 + (c^(r&7)))*16,
                Bp + (size_t)(n0+r)*(HD/8) + kc/8 + c);
        }
        cpa_commit();
        cpa_wait<0>();
        __syncthreads();

        #pragma unroll
        for (int ks = 0; ks < 8; ks++) {
            unsigned a_h[4];
            unsigned aaddr = su + (unsigned)(arow*16 + ((2*ks+abit) ^ (arow&7)))*16;
            ldsm4(a_h, aaddr);
            unsigned bh_[2][4];
            #pragma unroll
            for (int np = 0; np < 2; np++) {
                int brow = ncol0 + np*16 + kb;
                unsigned baddr = su + 16384u + (unsigned)(brow*16 + ((2*ks+kbit) ^ (brow&7)))*16;
                ldsm4(bh_[np], baddr);
            }
            #pragma unroll
            for (int np = 0; np < 2; np++) {
                mma16816h(acc[2*np],   a_h, bh_[np]);
                mma16816h(acc[2*np+1], a_h, bh_[np]+2);
            }
        }
    }

    #pragma unroll
    for (int nt = 0; nt < 4; nt++) {
        int n = n0 + ncol0 + nt*8 + 2*tig;
        float2 bb = *(const float2*)(bc + n);
        int ma = m0 + mrow0 + g;
        *(float2*)(out + (size_t)ma*128 + n) =
            make_float2(acc[nt][0] + bb.x, acc[nt][1] + bb.y);
        *(float2*)(out + (size_t)(ma+8)*128 + n) =
            make_float2(acc[nt][2] + bb.x, acc[nt][3] + bb.y);
    }
}

// ---------------------------------------------------------------------------
extern "C" void kernel_launch(void* const* d_in, const int* in_sizes, int n_in,
                              void* d_out, int out_size)
{
    const float* q    = (const float*)d_in[0];
    const float* k    = (const float*)d_in[1];
    const float* v    = (const float*)d_in[2];
    const float* mask = (const float*)d_in[3];
    const float* Wq   = (const float*)d_in[4];
    const float* Wk   = (const float*)d_in[5];
    const float* Wv   = (const float*)d_in[6];
    const float* Wc   = (const float*)d_in[7];
    const float* bc   = (const float*)d_in[8];
    float* out = (float*)d_out;

    const int qkv_smem  = 49152;
    const int attn_smem = 102400;
    const int outp_smem = 32768;

    cudaFuncSetAttribute(qkv_proj_kernel, cudaFuncAttributeMaxDynamicSharedMemorySize, qkv_smem);
    cudaFuncSetAttribute(attn_kernel, cudaFuncAttributeMaxDynamicSharedMemorySize, attn_smem);
    cudaFuncSetAttribute(out_proj_kernel, cudaFuncAttributeMaxDynamicSharedMemorySize, outp_smem);

    convert_kernel<<<dim3(96, 7), 256>>>(q, k, v, Wq, Wk, Wv, Wc);
    qkv_proj_kernel<<<dim3(8, 128, 3), 256, qkv_smem>>>();
    attn_kernel<<<dim3(8, 64), 256, attn_smem>>>(mask);
    out_proj_kernel<<<dim3(128, 2), 256, outp_smem>>>(bc, out);
}

// round 12
// speedup vs baseline: 2.8466x; 1.0097x over previous
#include <cuda_runtime.h>
#include <cuda_bf16.h>
#include <cuda_fp16.h>

#define BB 8
#define SS 1024
#define HH 8
#define DD 128
#define HD 1024

// ---- scratch planes (fp16 payload throughout) ----
__device__ __half g_Xq[(size_t)BB*SS*128];
__device__ __half g_Xk[(size_t)BB*SS*128];
__device__ __half g_Xv[(size_t)BB*SS*128];
__device__ __half g_Wq[HD*128], g_Wk[HD*128], g_Wv[HD*128];
__device__ __half g_Wc[128*HD];
__device__ __half g_Q[(size_t)BB*HH*SS*DD];
__device__ __half g_K[(size_t)BB*HH*SS*DD];
__device__ __half g_V[(size_t)BB*HH*SS*DD];
__device__ __half g_O[(size_t)BB*SS*HD];

// ---- helpers ----
__device__ __forceinline__ void mma16816h(float* c, const unsigned* a, const unsigned* b) {
    asm volatile(
        "mma.sync.aligned.m16n8k16.row.col.f32.f16.f16.f32 "
        "{%0,%1,%2,%3}, {%4,%5,%6,%7}, {%8,%9}, {%0,%1,%2,%3};\n"
        : "+f"(c[0]), "+f"(c[1]), "+f"(c[2]), "+f"(c[3])
        : "r"(a[0]), "r"(a[1]), "r"(a[2]), "r"(a[3]), "r"(b[0]), "r"(b[1]));
}
// fp16-accumulator variant (C/D packed f16x2)
__device__ __forceinline__ void mma16816hh(unsigned* c, const unsigned* a, const unsigned* b) {
    asm volatile(
        "mma.sync.aligned.m16n8k16.row.col.f16.f16.f16.f16 "
        "{%0,%1}, {%2,%3,%4,%5}, {%6,%7}, {%0,%1};\n"
        : "+r"(c[0]), "+r"(c[1])
        : "r"(a[0]), "r"(a[1]), "r"(a[2]), "r"(a[3]), "r"(b[0]), "r"(b[1]));
}
__device__ __forceinline__ void ldsm4(unsigned* r, unsigned addr) {
    asm volatile("ldmatrix.sync.aligned.m8n8.x4.shared.b16 {%0,%1,%2,%3}, [%4];"
        : "=r"(r[0]), "=r"(r[1]), "=r"(r[2]), "=r"(r[3]) : "r"(addr));
}
__device__ __forceinline__ void ldsm4t(unsigned* r, unsigned addr) {
    asm volatile("ldmatrix.sync.aligned.m8n8.x4.trans.shared.b16 {%0,%1,%2,%3}, [%4];"
        : "=r"(r[0]), "=r"(r[1]), "=r"(r[2]), "=r"(r[3]) : "r"(addr));
}
__device__ __forceinline__ unsigned cvth2(float hi, float lo) {
    unsigned r;
    asm("cvt.rn.f16x2.f32 %0, %1, %2;" : "=r"(r) : "f"(hi), "f"(lo));
    return r;
}
__device__ __forceinline__ void cpa(unsigned dst, const void* src) {
    asm volatile("cp.async.cg.shared.global [%0], [%1], 16;" :: "r"(dst), "l"(src));
}
__device__ __forceinline__ void cpa_commit() { asm volatile("cp.async.commit_group;"); }
template<int N> __device__ __forceinline__ void cpa_wait() {
    asm volatile("cp.async.wait_group %0;" :: "n"(N));
}

// ---------------------------------------------------------------------------
// Convert fp32 operands to single fp16 planes (one-time, memory-bound).
// ---------------------------------------------------------------------------
__global__ __launch_bounds__(256) void convert_kernel(
    const float* __restrict__ q, const float* __restrict__ k, const float* __restrict__ v,
    const float* __restrict__ Wq, const float* __restrict__ Wk, const float* __restrict__ Wv,
    const float* __restrict__ Wc)
{
    const float* src; __half* dh; int n4;
    switch (blockIdx.y) {
        case 0: src = q;  dh = g_Xq; n4 = BB*SS*128/4; break;
        case 1: src = k;  dh = g_Xk; n4 = BB*SS*128/4; break;
        case 2: src = v;  dh = g_Xv; n4 = BB*SS*128/4; break;
        case 3: src = Wq; dh = g_Wq; n4 = HD*128/4; break;
        case 4: src = Wk; dh = g_Wk; n4 = HD*128/4; break;
        case 5: src = Wv; dh = g_Wv; n4 = HD*128/4; break;
        default: src = Wc; dh = g_Wc; n4 = 128*HD/4; break;
    }
    for (int i = blockIdx.x*256 + threadIdx.x; i < n4; i += gridDim.x*256) {
        float4 f = ((const float4*)src)[i];
        ((uint2*)dh)[i] = make_uint2(cvth2(f.y, f.x), cvth2(f.w, f.z));
    }
}

// ---------------------------------------------------------------------------
// Fused QKV projection: single-term fp16 mma.sync (validated r11).
// ---------------------------------------------------------------------------
__global__ __launch_bounds__(256) void qkv_proj_kernel()
{
    extern __shared__ char smq[];
    const unsigned su = (unsigned)__cvta_generic_to_shared(smq);

    const uint4 *Xp, *Wp;
    __half* Oh;
    if (blockIdx.z == 0)      { Xp=(const uint4*)g_Xq; Wp=(const uint4*)g_Wq; Oh=g_Q; }
    else if (blockIdx.z == 1) { Xp=(const uint4*)g_Xk; Wp=(const uint4*)g_Wk; Oh=g_K; }
    else                      { Xp=(const uint4*)g_Xv; Wp=(const uint4*)g_Wv; Oh=g_V; }

    const int m0 = blockIdx.y * 64;
    const int h  = blockIdx.x;
    const int tid = threadIdx.x;
    const int lane = tid & 31;
    const int wid  = tid >> 5;
    const int band = wid & 3, side = wid >> 2;
    const int g    = lane >> 2, tig = lane & 3;

    #pragma unroll
    for (int t = 0; t < 4; t++) {
        int idx = tid + 256*t;
        int r = idx >> 4, c = idx & 15;
        cpa(su + (unsigned)(r*16 + (c^(r&7)))*16, Xp + (size_t)(m0+r)*16 + c);
    }
    #pragma unroll
    for (int t = 0; t < 8; t++) {
        int idx = tid + 256*t;
        int r = idx >> 4, c = idx & 15;
        cpa(su + 16384u + (unsigned)(r*16 + (c^(r&7)))*16, Wp + (size_t)(h*128+r)*16 + c);
    }
    cpa_commit();
    cpa_wait<0>();
    __syncthreads();

    float acc[8][4];
    #pragma unroll
    for (int nt = 0; nt < 8; nt++)
        #pragma unroll
        for (int c = 0; c < 4; c++) acc[nt][c] = 0.f;

    const int arow = band*16 + (lane & 7) + ((lane >> 3) & 1)*8;
    const int abit = lane >> 4;
    const int kb   = (lane & 7) + ((lane >> 4) & 1)*8;
    const int kbit = (lane >> 3) & 1;

    #pragma unroll
    for (int ks = 0; ks < 8; ks++) {
        unsigned a_h[4];
        unsigned aaddr = su + (unsigned)(arow*16 + ((2*ks+abit) ^ (arow&7)))*16;
        ldsm4(a_h, aaddr);
        unsigned bh_[4][4];
        #pragma unroll
        for (int np = 0; np < 4; np++) {
            int brow = side*64 + np*16 + kb;
            unsigned baddr = su + 16384u + (unsigned)(brow*16 + ((2*ks+kbit) ^ (brow&7)))*16;
            ldsm4(bh_[np], baddr);
        }
        #pragma unroll
        for (int np = 0; np < 4; np++) {
            mma16816h(acc[2*np],   a_h, bh_[np]);
            mma16816h(acc[2*np+1], a_h, bh_[np]+2);
        }
    }

    #pragma unroll
    for (int nt = 0; nt < 8; nt++) {
        int col = side*64 + nt*8 + 2*tig;
        int ma = m0 + band*16 + g;
        int mb2 = ma + 8;
        size_t offa = (((size_t)((ma  >> 10)*HH + h))*SS + (ma  & 1023))*DD + col;
        size_t offb = (((size_t)((mb2 >> 10)*HH + h))*SS + (mb2 & 1023))*DD + col;
        *(unsigned*)(Oh + offa) = cvth2(acc[nt][1], acc[nt][0]);
        *(unsigned*)(Oh + offb) = cvth2(acc[nt][3], acc[nt][2]);
    }
}

// ---------------------------------------------------------------------------
// Flash attention (r10/r11 structure): QK fp16-accum, PV fp16 w/ fp32 accum.
// 256 thr / 8 warps, cp.async double-buffered K/V, 2 CTAs/SM.
// smem: msk 0 (4KB), Q 4096 (32KB), KV0 36864 (32KB: K+0, V+16384),
//       KV1 69632 (32KB). Total 100KB.
// ---------------------------------------------------------------------------
__global__ __launch_bounds__(256, 2) void attn_kernel(const float* __restrict__ mask)
{
    extern __shared__ char sm[];
    float* msk_s = (float*)sm;
    const unsigned smem_u = (unsigned)__cvta_generic_to_shared(sm);
    const unsigned offQh = 4096u, KV0 = 36864u, KV1 = 69632u;

    const int tid  = threadIdx.x;
    const int lane = tid & 31;
    const int wid  = tid >> 5;
    const int wq0  = wid * 16;
    const int g    = lane >> 2;
    const int tig  = lane & 3;

    const int bh = blockIdx.y;
    const int b_ = bh >> 3, h = bh & 7;
    const int q0 = blockIdx.x * 128;

    const uint4* qh4 = (const uint4*)(g_Q + ((size_t)bh*SS + q0)*DD);
    const uint4* kh4 = (const uint4*)(g_K + (size_t)bh*SS*DD);
    const uint4* vh4 = (const uint4*)(g_V + (size_t)bh*SS*DD);
    const float* mb = mask + b_*SS;

    *(float4*)&msk_s[tid*4] = ((const float4*)mb)[tid];
    #pragma unroll
    for (int t = 0; t < 8; t++) {
        int idx = tid + 256*t;
        int r = idx >> 4, c = idx & 15;
        unsigned phys = (unsigned)(r*16 + (c ^ (r&7)))*16;
        *(uint4*)(sm + 4096 + phys) = qh4[idx];
    }
    {
        #pragma unroll
        for (int t = 0; t < 4; t++) {
            int idx = tid + 256*t;
            int r = idx >> 4, c = idx & 15;
            unsigned dst = smem_u + KV0 + (unsigned)(r*16 + (c^(r&7)))*16;
            cpa(dst,          kh4 + idx);
            cpa(dst + 16384u, vh4 + idx);
        }
        cpa_commit();
    }

    float o[16][4];
    #pragma unroll
    for (int nt = 0; nt < 16; nt++)
        #pragma unroll
        for (int c = 0; c < 4; c++) o[nt][c] = 0.f;

    float m0s = -3.0e38f, m1s = -3.0e38f, l0s = 0.f, l1s = 0.f;
    const float scale = 0.08838834764831845f;  // 1/sqrt(128)

    const int arow = wq0 + (lane & 7) + ((lane >> 3) & 1)*8;
    const int abit = lane >> 4;
    const int kbr  = (lane & 7) + ((lane >> 4) & 1)*8;
    const int kbit = (lane >> 3) & 1;
    const int vr   = (lane & 7) + ((lane >> 3) & 1)*8;
    const int vbit = (lane >> 4) & 1;

    for (int it = 0; it < 16; it++) {
        const int j0 = it*64;
        const unsigned kvcur = (it & 1) ? KV1 : KV0;
        if (it < 15) {
            const unsigned kvnxt = (it & 1) ? KV0 : KV1;
            #pragma unroll
            for (int t = 0; t < 4; t++) {
                int idx = tid + 256*t;
                int r = idx >> 4, c = idx & 15;
                unsigned dst = smem_u + kvnxt + (unsigned)(r*16 + (c^(r&7)))*16;
                int gi = (j0 + 64 + r)*16 + c;
                cpa(dst,          kh4 + gi);
                cpa(dst + 16384u, vh4 + gi);
            }
            cpa_commit();
            cpa_wait<1>();
        } else {
            cpa_wait<0>();
        }
        __syncthreads();

        // ---- S = Q K^T (fp16 accumulator, packed) ----
        unsigned sph[8][2];
        #pragma unroll
        for (int nt = 0; nt < 8; nt++) { sph[nt][0] = 0u; sph[nt][1] = 0u; }

        #pragma unroll
        for (int ks = 0; ks < 8; ks++) {
            unsigned a_h[4];
            unsigned aaddr = smem_u + offQh + (unsigned)(arow*16 + ((2*ks+abit) ^ (arow&7)))*16;
            ldsm4(a_h, aaddr);
            unsigned bh_[4][4];
            #pragma unroll
            for (int np = 0; np < 4; np++) {
                int brow = np*16 + kbr;
                unsigned baddr = smem_u + kvcur + (unsigned)(brow*16 + ((2*ks+kbit) ^ (brow&7)))*16;
                ldsm4(bh_[np], baddr);
            }
            #pragma unroll
            for (int np = 0; np < 4; np++) {
                mma16816hh(sph[2*np],   a_h, bh_[np]);
                mma16816hh(sph[2*np+1], a_h, bh_[np]+2);
            }
        }

        // unpack to fp32
        float sacc[8][4];
        #pragma unroll
        for (int nt = 0; nt < 8; nt++) {
            float2 f01 = __half22float2(*(__half2*)&sph[nt][0]);
            float2 f23 = __half22float2(*(__half2*)&sph[nt][1]);
            sacc[nt][0] = f01.x; sacc[nt][1] = f01.y;
            sacc[nt][2] = f23.x; sacc[nt][3] = f23.y;
        }

        // ---- online softmax (validated) ----
        float mx0 = -3.0e38f, mx1 = -3.0e38f;
        #pragma unroll
        for (int nt = 0; nt < 8; nt++) {
            float2 mk = *(float2*)&msk_s[j0 + nt*8 + 2*tig];
            sacc[nt][0] = sacc[nt][0]*scale + mk.x;
            sacc[nt][1] = sacc[nt][1]*scale + mk.y;
            sacc[nt][2] = sacc[nt][2]*scale + mk.x;
            sacc[nt][3] = sacc[nt][3]*scale + mk.y;
            mx0 = fmaxf(mx0, fmaxf(sacc[nt][0], sacc[nt][1]));
            mx1 = fmaxf(mx1, fmaxf(sacc[nt][2], sacc[nt][3]));
        }
        #pragma unroll
        for (int mskb = 1; mskb <= 2; mskb <<= 1) {
            mx0 = fmaxf(mx0, __shfl_xor_sync(0xffffffffu, mx0, mskb));
            mx1 = fmaxf(mx1, __shfl_xor_sync(0xffffffffu, mx1, mskb));
        }
        float mn0 = fmaxf(m0s, mx0), mn1 = fmaxf(m1s, mx1);
        float al0 = __expf(m0s - mn0), al1 = __expf(m1s - mn1);
        m0s = mn0; m1s = mn1;

        float sum0 = 0.f, sum1 = 0.f;
        #pragma unroll
        for (int nt = 0; nt < 8; nt++) {
            float p0 = __expf(sacc[nt][0] - mn0);
            float p1 = __expf(sacc[nt][1] - mn0);
            float p2 = __expf(sacc[nt][2] - mn1);
            float p3 = __expf(sacc[nt][3] - mn1);
            sacc[nt][0] = p0; sacc[nt][1] = p1; sacc[nt][2] = p2; sacc[nt][3] = p3;
            sum0 += p0 + p1; sum1 += p2 + p3;
        }
        #pragma unroll
        for (int mskb = 1; mskb <= 2; mskb <<= 1) {
            sum0 += __shfl_xor_sync(0xffffffffu, sum0, mskb);
            sum1 += __shfl_xor_sync(0xffffffffu, sum1, mskb);
        }
        l0s = l0s*al0 + sum0;
        l1s = l1s*al1 + sum1;

        #pragma unroll
        for (int nt = 0; nt < 16; nt++) {
            o[nt][0] *= al0; o[nt][1] *= al0;
            o[nt][2] *= al1; o[nt][3] *= al1;
        }

        // ---- O += P V (fp16 operands, fp32 accum) ----
        #pragma unroll
        for (int kk = 0; kk < 4; kk++) {
            unsigned pah[4];
            #pragma unroll
            for (int half = 0; half < 2; half++) {
                int nt = 2*kk + half;
                pah[2*half]   = cvth2(sacc[nt][1], sacc[nt][0]);
                pah[2*half+1] = cvth2(sacc[nt][3], sacc[nt][2]);
            }
            int vrow = kk*16 + vr;
            #pragma unroll
            for (int np = 0; np < 8; np++) {
                int vchk = 2*np + vbit;
                unsigned vaddr = smem_u + kvcur + 16384u
                               + (unsigned)(vrow*16 + (vchk ^ (vrow&7)))*16;
                unsigned vbh[4];
                ldsm4t(vbh, vaddr);
                mma16816h(o[2*np],   pah, vbh);
                mma16816h(o[2*np+1], pah, vbh+2);
            }
        }
        __syncthreads();
    }

    // epilogue: normalize, write single fp16 plane of O (concat [B,S,H*D])
    float inv0 = 1.f / (l0s + 1e-12f);
    float inv1 = 1.f / (l1s + 1e-12f);
    int r0 = q0 + wq0 + g;
    size_t base0 = ((size_t)(b_*SS + r0))*HD + h*DD;
    size_t base1 = base0 + (size_t)8*HD;
    #pragma unroll
    for (int nt = 0; nt < 16; nt++) {
        int cc = nt*8 + 2*tig;
        *(unsigned*)(g_O + base0 + cc) = cvth2(o[nt][1]*inv0, o[nt][0]*inv0);
        *(unsigned*)(g_O + base1 + cc) = cvth2(o[nt][3]*inv1, o[nt][2]*inv1);
    }
}

// ---------------------------------------------------------------------------
// Output projection: single-term fp16 mma.sync, 64x64 tiles, grid (128,2),
// double-buffered kc loop. smem: bufs A0 0 /B0 16384, A1 32768 /B1 49152 (64KB).
// ---------------------------------------------------------------------------
__global__ __launch_bounds__(256) void out_proj_kernel(
    const float* __restrict__ bc, float* __restrict__ out)
{
    extern __shared__ char smo[];
    const unsigned su = (unsigned)__cvta_generic_to_shared(smo);

    const int m0 = blockIdx.x * 64;
    const int n0 = blockIdx.y * 64;
    const int tid = threadIdx.x;
    const int lane = tid & 31;
    const int wid  = tid >> 5;
    const int mrow0 = (wid & 3)*16;
    const int ncol0 = (wid >> 2)*32;
    const int g = lane >> 2, tig = lane & 3;

    const int arow = mrow0 + (lane & 7) + ((lane >> 3) & 1)*8;
    const int abit = lane >> 4;
    const int kb   = (lane & 7) + ((lane >> 4) & 1)*8;
    const int kbit = (lane >> 3) & 1;

    float acc[4][4];
    #pragma unroll
    for (int nt = 0; nt < 4; nt++)
        #pragma unroll
        for (int c = 0; c < 4; c++) acc[nt][c] = 0.f;

    const uint4* Ap = (const uint4*)g_O;
    const uint4* Bp = (const uint4*)g_Wc;

    // prefetch chunk 0 into buf0
    {
        #pragma unroll
        for (int t = 0; t < 4; t++) {
            int idx = tid + 256*t;
            int r = idx >> 4, c = idx & 15;
            unsigned sw = (unsigned)(r*16 + (c^(r&7)))*16;
            cpa(su + sw,          Ap + (size_t)(m0+r)*(HD/8) + c);
            cpa(su + 16384u + sw, Bp + (size_t)(n0+r)*(HD/8) + c);
        }
        cpa_commit();
    }

    for (int i = 0; i < 8; i++) {
        const unsigned cur = (unsigned)(i & 1) * 32768u;
        if (i < 7) {
            const unsigned nxt = (unsigned)((i+1) & 1) * 32768u;
            int kc8 = (i+1) * 16;   // (kc in uint4 units)
            #pragma unroll
            for (int t = 0; t < 4; t++) {
                int idx = tid + 256*t;
                int r = idx >> 4, c = idx & 15;
                unsigned sw = (unsigned)(r*16 + (c^(r&7)))*16;
                cpa(su + nxt + sw,          Ap + (size_t)(m0+r)*(HD/8) + kc8 + c);
                cpa(su + nxt + 16384u + sw, Bp + (size_t)(n0+r)*(HD/8) + kc8 + c);
            }
            cpa_commit();
            cpa_wait<1>();
        } else {
            cpa_wait<0>();
        }
        __syncthreads();

        #pragma unroll
        for (int ks = 0; ks < 8; ks++) {
            unsigned a_h[4];
            unsigned aaddr = su + cur + (unsigned)(arow*16 + ((2*ks+abit) ^ (arow&7)))*16;
            ldsm4(a_h, aaddr);
            unsigned bh_[2][4];
            #pragma unroll
            for (int np = 0; np < 2; np++) {
                int brow = ncol0 + np*16 + kb;
                unsigned baddr = su + cur + 16384u + (unsigned)(brow*16 + ((2*ks+kbit) ^ (brow&7)))*16;
                ldsm4(bh_[np], baddr);
            }
            #pragma unroll
            for (int np = 0; np < 2; np++) {
                mma16816h(acc[2*np],   a_h, bh_[np]);
                mma16816h(acc[2*np+1], a_h, bh_[np]+2);
            }
        }
        __syncthreads();
    }

    #pragma unroll
    for (int nt = 0; nt < 4; nt++) {
        int n = n0 + ncol0 + nt*8 + 2*tig;
        float2 bb = *(const float2*)(bc + n);
        int ma = m0 + mrow0 + g;
        *(float2*)(out + (size_t)ma*128 + n) =
            make_float2(acc[nt][0] + bb.x, acc[nt][1] + bb.y);
        *(float2*)(out + (size_t)(ma+8)*128 + n) =
            make_float2(acc[nt][2] + bb.x, acc[nt][3] + bb.y);
    }
}

// ---------------------------------------------------------------------------
extern "C" void kernel_launch(void* const* d_in, const int* in_sizes, int n_in,
                              void* d_out, int out_size)
{
    const float* q    = (const float*)d_in[0];
    const float* k    = (const float*)d_in[1];
    const float* v    = (const float*)d_in[2];
    const float* mask = (const float*)d_in[3];
    const float* Wq   = (const float*)d_in[4];
    const float* Wk   = (const float*)d_in[5];
    const float* Wv   = (const float*)d_in[6];
    const float* Wc   = (const float*)d_in[7];
    const float* bc   = (const float*)d_in[8];
    float* out = (float*)d_out;

    const int qkv_smem  = 49152;
    const int attn_smem = 102400;
    const int outp_smem = 65536;

    cudaFuncSetAttribute(qkv_proj_kernel, cudaFuncAttributeMaxDynamicSharedMemorySize, qkv_smem);
    cudaFuncSetAttribute(attn_kernel, cudaFuncAttributeMaxDynamicSharedMemorySize, attn_smem);
    cudaFuncSetAttribute(out_proj_kernel, cudaFuncAttributeMaxDynamicSharedMemorySize, outp_smem);

    convert_kernel<<<dim3(96, 7), 256>>>(q, k, v, Wq, Wk, Wv, Wc);
    qkv_proj_kernel<<<dim3(8, 128, 3), 256, qkv_smem>>>();
    attn_kernel<<<dim3(8, 64), 256, attn_smem>>>(mask);
    out_proj_kernel<<<dim3(128, 2), 256, outp_smem>>>(bc, out);
}